// round 5
// baseline (speedup 1.0000x reference)
#include <cuda_runtime.h>
#include <cuda_bf16.h>
#include <mma.h>

#define N_TOK 131072
#define DIM   512
#define MEM   25
#define ALPHA 0.2f
#define MOM   0.8f

using namespace nvcuda;

// ---------------- scratch (device globals; no allocation) ----------------
__device__ __nv_bfloat16 g_Bbig[544 * 512];     // [alpha*W1^T ; alpha*cache@W2^T ; 0] bf16
__device__ __nv_bfloat16 g_cacheT[512 * 32];    // cache^T bf16, padded to 32 slots
__device__ float    g_cacheTf[512 * 32];        // cache^T fp32
__device__ float    g_ACW2[MEM * DIM];          // ALPHA * cache @ W2^T (fp32)
__device__ unsigned g_colmax[MEM];
__device__ float    g_segp[128 * 32 * 512];     // per-block scatter partials (unnormalized)
__device__ float    g_cntp[128 * 32];
__device__ float    g_losspart[1024];

__device__ __forceinline__ unsigned f2o(float f) {
    unsigned u = __float_as_uint(f);
    return (u & 0x80000000u) ? ~u : (u | 0x80000000u);
}
__device__ __forceinline__ float o2f(unsigned u) {
    return __uint_as_float((u & 0x80000000u) ? (u & 0x7FFFFFFFu) : ~u);
}
__device__ __forceinline__ float wredsum(float v) {
    v += __shfl_xor_sync(0xffffffffu, v, 16);
    v += __shfl_xor_sync(0xffffffffu, v, 8);
    v += __shfl_xor_sync(0xffffffffu, v, 4);
    v += __shfl_xor_sync(0xffffffffu, v, 2);
    v += __shfl_xor_sync(0xffffffffu, v, 1);
    return v;
}
__device__ __forceinline__ float wredmax(float v) {
    v = fmaxf(v, __shfl_xor_sync(0xffffffffu, v, 16));
    v = fmaxf(v, __shfl_xor_sync(0xffffffffu, v, 8));
    v = fmaxf(v, __shfl_xor_sync(0xffffffffu, v, 4));
    v = fmaxf(v, __shfl_xor_sync(0xffffffffu, v, 2));
    v = fmaxf(v, __shfl_xor_sync(0xffffffffu, v, 1));
    return v;
}

// ---------------- init ----------------
__global__ void k_init() {
    if (threadIdx.x < MEM) g_colmax[threadIdx.x] = 0u;
}

// ---------------- ACW2[m][o] = ALPHA * sum_k cache[m][k] * W[o][512+k] ----------------
__global__ void k_acw2(const float* __restrict__ W, const float* __restrict__ cache) {
    __shared__ float cs[DIM];
    int m = blockIdx.x;
    for (int id = threadIdx.x; id < DIM; id += blockDim.x) cs[id] = cache[m * DIM + id];
    __syncthreads();
    int lane = threadIdx.x & 31, wid = threadIdx.x >> 5;
    for (int j = wid * 64; j < wid * 64 + 64; j++) {
        float d = 0.f;
        #pragma unroll
        for (int t = 0; t < 16; t++) {
            int k = lane + 32 * t;
            d += cs[k] * W[(size_t)j * 1024 + 512 + k];
        }
        d = wredsum(d);
        if (lane == 0) g_ACW2[m * DIM + j] = ALPHA * d;
    }
}

// ---------------- Bbig build ----------------
__global__ void k_prepB(const float* __restrict__ W) {
    int id = blockIdx.x * 256 + threadIdx.x;
    if (id >= 544 * 512) return;
    int r = id >> 9, o = id & 511;
    float v;
    if (r < 512)            v = ALPHA * W[(size_t)o * 1024 + r];
    else if (r < 512 + MEM) v = g_ACW2[(r - 512) * 512 + o];
    else                    v = 0.f;
    g_Bbig[id] = __float2bfloat16(v);
}

__global__ void k_prepC(const float* __restrict__ cache) {
    int id = blockIdx.x * 256 + threadIdx.x;
    if (id >= 512 * 32) return;
    int k = id >> 5, m = id & 31;
    float v = (m < MEM) ? cache[m * DIM + k] : 0.f;
    g_cacheT[id] = __float2bfloat16(v);
    g_cacheTf[id] = v;
}

// ---------------- fused: norm + score MMA + softmax + [text|p]@Bbig + residual + loss ----------------
// smem: A bf16 [128][552] 141312 B | B region 69632 B (Bs bf16[544][64] / {Ct, Ssm}) | rowss[128]
__global__ void __launch_bounds__(256) k_fused(const float* __restrict__ text,
                                               float* __restrict__ out) {
    extern __shared__ unsigned char smem_raw[];
    __nv_bfloat16* A  = (__nv_bfloat16*)smem_raw;
    unsigned char* Br = smem_raw + 141312;
    __nv_bfloat16* Bs = (__nv_bfloat16*)Br;
    __nv_bfloat16* Ct = (__nv_bfloat16*)Br;
    float* Ssm   = (float*)(Br + 32768);
    float* rowss = (float*)(smem_raw + 141312 + 69632);

    int tid = threadIdx.x, lane = tid & 31, wid = tid >> 5;
    int row0 = blockIdx.x * 128;
    const float4* t4 = (const float4*)text;

    if (tid < 128) rowss[tid] = 0.f;
    __syncthreads();

    // stage 1: load text fp32 -> bf16 tile + row sumsq
    for (int it = 0; it < 64; it++) {
        int id = it * 256 + tid;
        int r = id >> 7, c = id & 127;
        float4 v = t4[(size_t)(row0 + r) * 128 + c];
        float ss = v.x * v.x + v.y * v.y + v.z * v.z + v.w * v.w;
        ss = wredsum(ss);
        if (lane == 0) atomicAdd(&rowss[r], ss);
        __nv_bfloat162* dst = (__nv_bfloat162*)(A + r * 552 + c * 4);
        dst[0] = __floats2bfloat162_rn(v.x, v.y);
        dst[1] = __floats2bfloat162_rn(v.z, v.w);
    }
    for (int id = tid; id < 128 * 40; id += 256) {
        int r = id / 40, c = 512 + id % 40;
        A[r * 552 + c] = __float2bfloat16(0.f);
    }
    {
        const float4* src = (const float4*)g_cacheT;
        float4* dst = (float4*)Ct;
        for (int id = tid; id < 2048; id += 256) dst[id] = src[id];
    }
    __syncthreads();

    // stage 2: score MMA  S[128x32] = A(text) @ cacheT
    {
        wmma::fragment<wmma::accumulator, 16, 16, 16, float> sacc[2];
        wmma::fill_fragment(sacc[0], 0.f);
        wmma::fill_fragment(sacc[1], 0.f);
        for (int k0 = 0; k0 < 512; k0 += 16) {
            wmma::fragment<wmma::matrix_a, 16, 16, 16, __nv_bfloat16, wmma::row_major> af;
            wmma::load_matrix_sync(af, A + (wid * 16) * 552 + k0, 552);
            #pragma unroll
            for (int j = 0; j < 2; j++) {
                wmma::fragment<wmma::matrix_b, 16, 16, 16, __nv_bfloat16, wmma::row_major> bf;
                wmma::load_matrix_sync(bf, Ct + k0 * 32 + j * 16, 32);
                wmma::mma_sync(sacc[j], af, bf, sacc[j]);
            }
        }
        wmma::store_matrix_sync(Ssm + (wid * 16) * 36, sacc[0], 36, wmma::mem_row_major);
        wmma::store_matrix_sync(Ssm + (wid * 16) * 36 + 16, sacc[1], 36, wmma::mem_row_major);
    }
    __syncthreads();

    // stage 3: softmax -> p into A cols 512..536
    for (int rr = 0; rr < 16; rr++) {
        int r = wid * 16 + rr;
        float rinv = 1.f / fmaxf(sqrtf(rowss[r]), 1e-12f);
        float s = (lane < MEM) ? Ssm[r * 36 + lane] * rinv : -1e30f;
        float mx = wredmax(s);
        float e = (lane < MEM) ? expf(s - mx) : 0.f;
        float sum = wredsum(e);
        if (lane < MEM) A[r * 552 + 512 + lane] = __float2bfloat16(e / sum);
    }
    __syncthreads();

    // stage 4: out = text + A @ Bbig  (acc preloaded with text, stored directly to out)
    int wr = wid & 3, wc = wid >> 2;
    for (int cb = 0; cb < 8; cb++) {
        int col0 = cb * 64;
        for (int id = tid; id < 544 * 8; id += 256) {
            int r = id >> 3, g = id & 7;
            ((float4*)Bs)[r * 8 + g] = ((const float4*)g_Bbig)[r * 64 + (col0 >> 3) + g];
        }
        __syncthreads();
        wmma::fragment<wmma::accumulator, 16, 16, 16, float> acc[2][2];
        #pragma unroll
        for (int i = 0; i < 2; i++)
            #pragma unroll
            for (int j = 0; j < 2; j++)
                wmma::load_matrix_sync(acc[i][j],
                    text + (size_t)(row0 + wr * 32 + i * 16) * DIM + col0 + wc * 32 + j * 16,
                    DIM, wmma::mem_row_major);
        for (int k0 = 0; k0 < 544; k0 += 16) {
            wmma::fragment<wmma::matrix_a, 16, 16, 16, __nv_bfloat16, wmma::row_major> af[2];
            wmma::fragment<wmma::matrix_b, 16, 16, 16, __nv_bfloat16, wmma::row_major> bf[2];
            #pragma unroll
            for (int i = 0; i < 2; i++)
                wmma::load_matrix_sync(af[i], A + (wr * 32 + i * 16) * 552 + k0, 552);
            #pragma unroll
            for (int j = 0; j < 2; j++)
                wmma::load_matrix_sync(bf[j], Bs + k0 * 64 + wc * 32 + j * 16, 64);
            #pragma unroll
            for (int i = 0; i < 2; i++)
                #pragma unroll
                for (int j = 0; j < 2; j++)
                    wmma::mma_sync(acc[i][j], af[i], bf[j], acc[i][j]);
        }
        #pragma unroll
        for (int i = 0; i < 2; i++)
            #pragma unroll
            for (int j = 0; j < 2; j++)
                wmma::store_matrix_sync(
                    out + (size_t)(row0 + wr * 32 + i * 16) * DIM + col0 + wc * 32 + j * 16,
                    acc[i][j], DIM, wmma::mem_row_major);
        __syncthreads();   // Bs reuse next chunk
    }

    // stage 5: loss partial over this block's 128 rows (out tile is L2-hot)
    {
        const float4* o4 = (const float4*)out;
        float accum = 0.f;
        #pragma unroll
        for (int rr = 0; rr < 16; rr++) {
            int i = row0 + wid * 16 + rr;
            float4 tf[4]; float ss = 0.f;
            #pragma unroll
            for (int t = 0; t < 4; t++) {
                tf[t] = o4[(size_t)i * 128 + lane + 32 * t];
                ss += tf[t].x * tf[t].x + tf[t].y * tf[t].y + tf[t].z * tf[t].z + tf[t].w * tf[t].w;
            }
            ss = wredsum(ss);
            float inv = 1.f / fmaxf(sqrtf(ss), 1e-12f);
            float sa = 0.f;
            #pragma unroll
            for (int t = 0; t < 4; t++) {
                float4 x = t4[(size_t)i * 128 + lane + 32 * t];
                sa += fabsf(tf[t].x * inv - x.x) + fabsf(tf[t].y * inv - x.y) +
                      fabsf(tf[t].z * inv - x.z) + fabsf(tf[t].w * inv - x.w);
            }
            accum += wredsum(sa);
        }
        __shared__ float ws[8];
        if (lane == 0) ws[wid] = accum;
        __syncthreads();
        if (tid == 0) {
            float s = 0.f;
            #pragma unroll
            for (int w = 0; w < 8; w++) s += ws[w];
            g_losspart[blockIdx.x] = s;
        }
    }
}

__global__ void k_loss2(float* __restrict__ out) {
    __shared__ float sh[256];
    int tid = threadIdx.x;
    float s = 0.f;
    for (int id = tid; id < 1024; id += 256) s += g_losspart[id];
    sh[tid] = s;
    __syncthreads();
    for (int off = 128; off > 0; off >>= 1) {
        if (tid < off) sh[tid] += sh[tid + off];
        __syncthreads();
    }
    if (tid == 0) out[(size_t)N_TOK * DIM] = sh[0] * (1.0f / 67108864.0f);
}

// ---------------- fused write: img attention (tf32 big+small) + one-hot scatter MMA ----------------
// smem: Bimg f32[64][520] 133120 | CtF f32[512][32] 65536 | Aw f32[32][72] 9216 | Ssm f32[64][36] 9216
__global__ void __launch_bounds__(256) k_write(const float* __restrict__ img) {
    extern __shared__ unsigned char sraw[];
    float* Bimg = (float*)sraw;
    float* CtF  = (float*)(sraw + 133120);
    float* Aw   = (float*)(sraw + 133120 + 65536);
    float* Ssm  = (float*)(sraw + 133120 + 65536 + 9216);
    __shared__ float cnts[32];
    __shared__ float rinv_s[64];
    __shared__ unsigned cm_u[MEM];

    int tid = threadIdx.x, wid = tid >> 5;
    if (tid < 32) cnts[tid] = 0.f;
    if (tid < MEM) cm_u[tid] = 0u;

    // load cache^T fp32 once
    {
        const float4* src = (const float4*)g_cacheTf;
        float4* dst = (float4*)CtF;
        for (int id = tid; id < 4096; id += 256) dst[id] = src[id];
    }

    float cmreg[MEM];
    #pragma unroll
    for (int m = 0; m < MEM; m++) cmreg[m] = -1e30f;

    wmma::fragment<wmma::accumulator, 16, 16, 8, float> acc[2][4];
    #pragma unroll
    for (int i = 0; i < 2; i++)
        #pragma unroll
        for (int j = 0; j < 4; j++) wmma::fill_fragment(acc[i][j], 0.f);

    const float4* i4 = (const float4*)img;
    for (int tile = 0; tile < 16; tile++) {
        int base = blockIdx.x * 1024 + tile * 64;
        for (int id = tid; id < 64 * 128; id += 256) {
            int r = id >> 7, c = id & 127;
            *((float4*)&Bimg[r * 520 + c * 4]) = i4[(size_t)(base + r) * 128 + c];
        }
        for (int id = tid; id < 32 * 72; id += 256) Aw[id] = 0.f;
        __syncthreads();

        // row sumsq: 4 threads per row
        {
            int r = tid >> 2, q = tid & 3;
            const float4* row = (const float4*)&Bimg[r * 520];
            float ss = 0.f;
            #pragma unroll
            for (int t = 0; t < 32; t++) {
                float4 v = row[q * 32 + t];
                ss += v.x * v.x + v.y * v.y + v.z * v.z + v.w * v.w;
            }
            ss += __shfl_xor_sync(0xffffffffu, ss, 1);
            ss += __shfl_xor_sync(0xffffffffu, ss, 2);
            if (q == 0) rinv_s[r] = rsqrtf(ss);
        }

        // score MMA (tf32 big+small): S[64x32] = Bimg @ CtF
        {
            int rowt = wid >> 1, colt = wid & 1;
            wmma::fragment<wmma::accumulator, 16, 16, 8, float> sacc;
            wmma::fill_fragment(sacc, 0.f);
            for (int k0 = 0; k0 < 512; k0 += 8) {
                wmma::fragment<wmma::matrix_a, 16, 16, 8, wmma::precision::tf32, wmma::row_major> ab, as;
                wmma::fragment<wmma::matrix_b, 16, 16, 8, wmma::precision::tf32, wmma::row_major> bb, bs;
                wmma::load_matrix_sync(ab, Bimg + (rowt * 16) * 520 + k0, 520);
                wmma::load_matrix_sync(bb, CtF + k0 * 32 + colt * 16, 32);
                #pragma unroll
                for (int t = 0; t < ab.num_elements; t++) {
                    float x = ab.x[t];
                    float big = wmma::__float_to_tf32(x);
                    ab.x[t] = big;
                    as.x[t] = wmma::__float_to_tf32(x - big);
                }
                #pragma unroll
                for (int t = 0; t < bb.num_elements; t++) {
                    float x = bb.x[t];
                    float big = wmma::__float_to_tf32(x);
                    bb.x[t] = big;
                    bs.x[t] = wmma::__float_to_tf32(x - big);
                }
                wmma::mma_sync(sacc, ab, bs, sacc);
                wmma::mma_sync(sacc, as, bb, sacc);
                wmma::mma_sync(sacc, ab, bb, sacc);
            }
            wmma::store_matrix_sync(Ssm + (rowt * 16) * 36 + colt * 16, sacc, 36,
                                    wmma::mem_row_major);
        }
        __syncthreads();

        // argmax + one-hot weight (unnormalized: exp(s)*rinv; colmax applied in k_update)
        if (tid < 64) {
            float rv = rinv_s[tid];
            float best = -1e30f; int bi = 0;
            #pragma unroll
            for (int m = 0; m < MEM; m++) {
                float v = Ssm[tid * 36 + m] * rv;
                cmreg[m] = fmaxf(cmreg[m], v);
                if (v > best) { best = v; bi = m; }
            }
            Aw[bi * 72 + tid] = __expf(best) * rv;
            atomicAdd(&cnts[bi], 1.f);
        }
        __syncthreads();

        // scatter MMA: acc += Aw(one-hot) @ Bimg
        for (int ks = 0; ks < 8; ks++) {
            int k0 = ks * 8;
            wmma::fragment<wmma::matrix_a, 16, 16, 8, wmma::precision::tf32, wmma::row_major> af[2];
            wmma::fragment<wmma::matrix_b, 16, 16, 8, wmma::precision::tf32, wmma::row_major> bf[4];
            #pragma unroll
            for (int i = 0; i < 2; i++) {
                wmma::load_matrix_sync(af[i], Aw + (i * 16) * 72 + k0, 72);
                #pragma unroll
                for (int t = 0; t < af[i].num_elements; t++)
                    af[i].x[t] = wmma::__float_to_tf32(af[i].x[t]);
            }
            #pragma unroll
            for (int j = 0; j < 4; j++) {
                wmma::load_matrix_sync(bf[j], Bimg + k0 * 520 + wid * 64 + j * 16, 520);
                #pragma unroll
                for (int t = 0; t < bf[j].num_elements; t++)
                    bf[j].x[t] = wmma::__float_to_tf32(bf[j].x[t]);
            }
            #pragma unroll
            for (int i = 0; i < 2; i++)
                #pragma unroll
                for (int j = 0; j < 4; j++)
                    wmma::mma_sync(acc[i][j], af[i], bf[j], acc[i][j]);
        }
        __syncthreads();
    }

    #pragma unroll
    for (int i = 0; i < 2; i++)
        #pragma unroll
        for (int j = 0; j < 4; j++)
            wmma::store_matrix_sync(g_segp + (size_t)blockIdx.x * 16384 + (i * 16) * 512 +
                                    wid * 64 + j * 16, acc[i][j], 512, wmma::mem_row_major);
    if (tid < 32) g_cntp[blockIdx.x * 32 + tid] = cnts[tid];

    // merge column maxes: block-local then global
    if (tid < 64) {
        #pragma unroll
        for (int m = 0; m < MEM; m++) atomicMax(&cm_u[m], f2o(cmreg[m]));
    }
    __syncthreads();
    if (tid < MEM) atomicMax(&g_colmax[tid], cm_u[tid]);
}

// ---------------- cache EMA update + normalize (applies exp(-colmax)) ----------------
__global__ void k_update(const float* __restrict__ cache, float* __restrict__ out) {
    int m = blockIdx.x, d = threadIdx.x;
    float cnt = 0.f;
    for (int b = 0; b < 128; b++) cnt += g_cntp[b * 32 + m];
    float s = 0.f;
    for (int b = 0; b < 128; b++) s += g_segp[(size_t)b * 16384 + m * 512 + d];
    float cm = o2f(g_colmax[m]);
    s *= __expf(-cm);
    float cv = cache[m * DIM + d];
    float u = (cnt > 0.f) ? (MOM * cv + (1.f - MOM) * s) : cv;
    float v = u * u;
    v = wredsum(v);
    __shared__ float red[16];
    __shared__ float tot;
    if ((threadIdx.x & 31) == 0) red[threadIdx.x >> 5] = v;
    __syncthreads();
    if (threadIdx.x < 32) {
        float t = (threadIdx.x < 16) ? red[threadIdx.x] : 0.f;
        t = wredsum(t);
        if (threadIdx.x == 0) tot = t;
    }
    __syncthreads();
    float inv = 1.f / fmaxf(sqrtf(tot), 1e-12f);
    out[(size_t)N_TOK * DIM + 1 + m * DIM + d] = u * inv;
}

// ---------------- launch ----------------
extern "C" void kernel_launch(void* const* d_in, const int* in_sizes, int n_in,
                              void* d_out, int out_size) {
    const float* text  = (const float*)d_in[0];
    const float* img   = (const float*)d_in[1];
    const float* W     = (const float*)d_in[2];
    const float* cache = (const float*)d_in[3];
    float* out = (float*)d_out;

    const int FUSED_SMEM = 141312 + 69632 + 512;                 // 211456
    const int WRITE_SMEM = 133120 + 65536 + 9216 + 9216;         // 217088

    cudaFuncSetAttribute(k_fused, cudaFuncAttributeMaxDynamicSharedMemorySize, FUSED_SMEM);
    cudaFuncSetAttribute(k_write, cudaFuncAttributeMaxDynamicSharedMemorySize, WRITE_SMEM);

    k_init<<<1, 32>>>();
    k_acw2<<<MEM, 256>>>(W, cache);
    k_prepB<<<(544 * 512 + 255) / 256, 256>>>(W);
    k_prepC<<<(512 * 32 + 255) / 256, 256>>>(cache);
    k_write<<<128, 256, WRITE_SMEM>>>(img);
    k_fused<<<1024, 256, FUSED_SMEM>>>(text, out);
    k_loss2<<<1, 256>>>(out);
    k_update<<<MEM, 512>>>(cache, out);
}

// round 7
// speedup vs baseline: 1.0271x; 1.0271x over previous
#include <cuda_runtime.h>
#include <cuda_bf16.h>
#include <mma.h>

#define N_TOK 131072
#define DIM   512
#define MEM   25
#define ALPHA 0.2f
#define MOM   0.8f
#define WBLK  148

using namespace nvcuda;

// ---------------- scratch (device globals; no allocation) ----------------
__device__ __nv_bfloat16 g_Bbig[544 * 512];     // [alpha*W1^T ; alpha*cache@W2^T ; 0] bf16
__device__ __nv_bfloat16 g_cacheT[512 * 32];    // cache^T bf16, padded to 32 slots
__device__ float    g_cacheTf[512 * 32];        // cache^T fp32
__device__ float    g_ACW2[MEM * DIM];          // ALPHA * cache @ W2^T (fp32)
__device__ unsigned g_colmax[MEM];
__device__ float    g_segp[WBLK * 32 * 512];    // per-block scatter partials (unnormalized)
__device__ float    g_cntp[WBLK * 32];
__device__ float    g_losspart[1024];

__device__ __forceinline__ unsigned f2o(float f) {
    unsigned u = __float_as_uint(f);
    return (u & 0x80000000u) ? ~u : (u | 0x80000000u);
}
__device__ __forceinline__ float o2f(unsigned u) {
    return __uint_as_float((u & 0x80000000u) ? (u & 0x7FFFFFFFu) : ~u);
}
__device__ __forceinline__ float wredsum(float v) {
    v += __shfl_xor_sync(0xffffffffu, v, 16);
    v += __shfl_xor_sync(0xffffffffu, v, 8);
    v += __shfl_xor_sync(0xffffffffu, v, 4);
    v += __shfl_xor_sync(0xffffffffu, v, 2);
    v += __shfl_xor_sync(0xffffffffu, v, 1);
    return v;
}
__device__ __forceinline__ float wredmax(float v) {
    v = fmaxf(v, __shfl_xor_sync(0xffffffffu, v, 16));
    v = fmaxf(v, __shfl_xor_sync(0xffffffffu, v, 8));
    v = fmaxf(v, __shfl_xor_sync(0xffffffffu, v, 4));
    v = fmaxf(v, __shfl_xor_sync(0xffffffffu, v, 2));
    v = fmaxf(v, __shfl_xor_sync(0xffffffffu, v, 1));
    return v;
}

// ---------------- launch 1: ACW2 + colmax init ----------------
__global__ void k_acw2(const float* __restrict__ W, const float* __restrict__ cache) {
    __shared__ float cs[DIM];
    int m = blockIdx.x;
    if (blockIdx.x == 0 && threadIdx.x < MEM) g_colmax[threadIdx.x] = 0u;
    for (int id = threadIdx.x; id < DIM; id += blockDim.x) cs[id] = cache[m * DIM + id];
    __syncthreads();
    int lane = threadIdx.x & 31, wid = threadIdx.x >> 5;
    for (int j = wid * 64; j < wid * 64 + 64; j++) {
        float d = 0.f;
        #pragma unroll
        for (int t = 0; t < 16; t++) {
            int k = lane + 32 * t;
            d += cs[k] * W[(size_t)j * 1024 + 512 + k];
        }
        d = wredsum(d);
        if (lane == 0) g_ACW2[m * DIM + j] = ALPHA * d;
    }
}

// ---------------- launch 2: Bbig build ----------------
__global__ void k_prepB(const float* __restrict__ W) {
    int id = blockIdx.x * 256 + threadIdx.x;
    if (id >= 544 * 512) return;
    int r = id >> 9, o = id & 511;
    float v;
    if (r < 512)            v = ALPHA * W[(size_t)o * 1024 + r];
    else if (r < 512 + MEM) v = g_ACW2[(r - 512) * 512 + o];
    else                    v = 0.f;
    g_Bbig[id] = __float2bfloat16(v);
}

// ---------------- launch 3: cache^T prep ----------------
__global__ void k_prepC(const float* __restrict__ cache) {
    int id = blockIdx.x * 256 + threadIdx.x;
    if (id >= 512 * 32) return;
    int k = id >> 5, m = id & 31;
    float v = (m < MEM) ? cache[m * DIM + k] : 0.f;
    g_cacheT[id] = __float2bfloat16(v);
    g_cacheTf[id] = v;
}

// ---------------- launch 4 (profiled): norm + score + softmax + GEMM + residual + loss ----------------
// smem: A bf16 [128][552] 141312 | B region 69632 (Bs bf16[544][64] / {Ct,Ssm} / Cs f32[128][68]) | rowss[128]
__global__ void __launch_bounds__(256) k_fused(const float* __restrict__ text,
                                               float* __restrict__ out) {
    extern __shared__ unsigned char smem_raw[];
    __nv_bfloat16* A  = (__nv_bfloat16*)smem_raw;
    unsigned char* Br = smem_raw + 141312;
    __nv_bfloat16* Bs = (__nv_bfloat16*)Br;
    __nv_bfloat16* Ct = (__nv_bfloat16*)Br;
    float* Ssm   = (float*)(Br + 32768);
    float* Cs    = (float*)Br;
    float* rowss = (float*)(smem_raw + 141312 + 69632);

    int tid = threadIdx.x, lane = tid & 31, wid = tid >> 5;
    int row0 = blockIdx.x * 128;
    const float4* t4 = (const float4*)text;

    if (tid < 128) rowss[tid] = 0.f;
    __syncthreads();

    // stage 1: text -> bf16 tile + row sumsq
    for (int it = 0; it < 64; it++) {
        int id = it * 256 + tid;
        int r = id >> 7, c = id & 127;
        float4 v = t4[(size_t)(row0 + r) * 128 + c];
        float ss = v.x * v.x + v.y * v.y + v.z * v.z + v.w * v.w;
        ss = wredsum(ss);
        if (lane == 0) atomicAdd(&rowss[r], ss);
        __nv_bfloat162* dst = (__nv_bfloat162*)(A + r * 552 + c * 4);
        dst[0] = __floats2bfloat162_rn(v.x, v.y);
        dst[1] = __floats2bfloat162_rn(v.z, v.w);
    }
    for (int id = tid; id < 128 * 40; id += 256) {
        int r = id / 40, c = 512 + id % 40;
        A[r * 552 + c] = __float2bfloat16(0.f);
    }
    {
        const float4* src = (const float4*)g_cacheT;
        float4* dst = (float4*)Ct;
        for (int id = tid; id < 2048; id += 256) dst[id] = src[id];
    }
    __syncthreads();

    // stage 2: score MMA  S[128x32] = A(text) @ cacheT
    {
        wmma::fragment<wmma::accumulator, 16, 16, 16, float> sacc[2];
        wmma::fill_fragment(sacc[0], 0.f);
        wmma::fill_fragment(sacc[1], 0.f);
        for (int k0 = 0; k0 < 512; k0 += 16) {
            wmma::fragment<wmma::matrix_a, 16, 16, 16, __nv_bfloat16, wmma::row_major> af;
            wmma::load_matrix_sync(af, A + (wid * 16) * 552 + k0, 552);
            #pragma unroll
            for (int j = 0; j < 2; j++) {
                wmma::fragment<wmma::matrix_b, 16, 16, 16, __nv_bfloat16, wmma::row_major> bf;
                wmma::load_matrix_sync(bf, Ct + k0 * 32 + j * 16, 32);
                wmma::mma_sync(sacc[j], af, bf, sacc[j]);
            }
        }
        wmma::store_matrix_sync(Ssm + (wid * 16) * 36, sacc[0], 36, wmma::mem_row_major);
        wmma::store_matrix_sync(Ssm + (wid * 16) * 36 + 16, sacc[1], 36, wmma::mem_row_major);
    }
    __syncthreads();

    // stage 3: softmax -> p into A cols 512..536
    for (int rr = 0; rr < 16; rr++) {
        int r = wid * 16 + rr;
        float rinv = 1.f / fmaxf(sqrtf(rowss[r]), 1e-12f);
        float s = (lane < MEM) ? Ssm[r * 36 + lane] * rinv : -1e30f;
        float mx = wredmax(s);
        float e = (lane < MEM) ? expf(s - mx) : 0.f;
        float sum = wredsum(e);
        if (lane < MEM) A[r * 552 + 512 + lane] = __float2bfloat16(e / sum);
    }
    __syncthreads();

    // stage 4: out = ([text|p] @ Bbig) + text, smem-staged epilogue
    int wr = wid & 3, wc = wid >> 2;
    for (int cb = 0; cb < 8; cb++) {
        int col0 = cb * 64;
        for (int id = tid; id < 544 * 8; id += 256) {
            int r = id >> 3, g = id & 7;
            ((float4*)Bs)[r * 8 + g] = ((const float4*)g_Bbig)[r * 64 + (col0 >> 3) + g];
        }
        __syncthreads();
        wmma::fragment<wmma::accumulator, 16, 16, 16, float> acc[2][2];
        #pragma unroll
        for (int i = 0; i < 2; i++)
            #pragma unroll
            for (int j = 0; j < 2; j++) wmma::fill_fragment(acc[i][j], 0.f);
        for (int k0 = 0; k0 < 544; k0 += 16) {
            wmma::fragment<wmma::matrix_a, 16, 16, 16, __nv_bfloat16, wmma::row_major> af[2];
            wmma::fragment<wmma::matrix_b, 16, 16, 16, __nv_bfloat16, wmma::row_major> bf[2];
            #pragma unroll
            for (int i = 0; i < 2; i++)
                wmma::load_matrix_sync(af[i], A + (wr * 32 + i * 16) * 552 + k0, 552);
            #pragma unroll
            for (int j = 0; j < 2; j++)
                wmma::load_matrix_sync(bf[j], Bs + k0 * 64 + wc * 32 + j * 16, 64);
            #pragma unroll
            for (int i = 0; i < 2; i++)
                #pragma unroll
                for (int j = 0; j < 2; j++)
                    wmma::mma_sync(acc[i][j], af[i], bf[j], acc[i][j]);
        }
        __syncthreads();   // done reading Bs before Cs overwrites it
        #pragma unroll
        for (int i = 0; i < 2; i++)
            #pragma unroll
            for (int j = 0; j < 2; j++)
                wmma::store_matrix_sync(Cs + (wr * 32 + i * 16) * 68 + wc * 32 + j * 16,
                                        acc[i][j], 68, wmma::mem_row_major);
        __syncthreads();
        for (int it = 0; it < 8; it++) {
            int id = it * 256 + tid;
            int r = id >> 4, q = id & 15;
            float4 v = *((float4*)&Cs[r * 68 + q * 4]);
            float4 t = t4[(size_t)(row0 + r) * 128 + (col0 >> 2) + q];
            v.x += t.x; v.y += t.y; v.z += t.z; v.w += t.w;
            ((float4*)out)[(size_t)(row0 + r) * 128 + (col0 >> 2) + q] = v;
        }
        __syncthreads();
    }

    // stage 5: loss partial over this block's 128 rows (out tile is L2-hot)
    {
        const float4* o4 = (const float4*)out;
        float accum = 0.f;
        #pragma unroll
        for (int rr = 0; rr < 16; rr++) {
            int i = row0 + wid * 16 + rr;
            float4 tf[4]; float ss = 0.f;
            #pragma unroll
            for (int t = 0; t < 4; t++) {
                tf[t] = o4[(size_t)i * 128 + lane + 32 * t];
                ss += tf[t].x * tf[t].x + tf[t].y * tf[t].y + tf[t].z * tf[t].z + tf[t].w * tf[t].w;
            }
            ss = wredsum(ss);
            float inv = 1.f / fmaxf(sqrtf(ss), 1e-12f);
            float sa = 0.f;
            #pragma unroll
            for (int t = 0; t < 4; t++) {
                float4 x = t4[(size_t)i * 128 + lane + 32 * t];
                sa += fabsf(tf[t].x * inv - x.x) + fabsf(tf[t].y * inv - x.y) +
                      fabsf(tf[t].z * inv - x.z) + fabsf(tf[t].w * inv - x.w);
            }
            accum += wredsum(sa);
        }
        __shared__ float ws[8];
        if (lane == 0) ws[wid] = accum;
        __syncthreads();
        if (tid == 0) {
            float s = 0.f;
            #pragma unroll
            for (int w = 0; w < 8; w++) s += ws[w];
            g_losspart[blockIdx.x] = s;
        }
    }
}

__global__ void k_loss2(float* __restrict__ out) {
    __shared__ float sh[256];
    int tid = threadIdx.x;
    float s = 0.f;
    for (int id = tid; id < 1024; id += 256) s += g_losspart[id];
    sh[tid] = s;
    __syncthreads();
    for (int off = 128; off > 0; off >>= 1) {
        if (tid < off) sh[tid] += sh[tid + off];
        __syncthreads();
    }
    if (tid == 0) out[(size_t)N_TOK * DIM] = sh[0] * (1.0f / 67108864.0f);
}

// ---------------- fused write: img attention (tf32 big+small split) + one-hot scatter MMA ----------------
// smem: Bimg f32[64][520] 133120 | CtF f32[512][32] 65536 | Aw f32[32][72] 9216 | Ssm f32[64][36] 9216
__global__ void __launch_bounds__(256) k_write(const float* __restrict__ img) {
    extern __shared__ unsigned char sraw[];
    float* Bimg = (float*)sraw;
    float* CtF  = (float*)(sraw + 133120);
    float* Aw   = (float*)(sraw + 133120 + 65536);
    float* Ssm  = (float*)(sraw + 133120 + 65536 + 9216);
    __shared__ float cnts[32];
    __shared__ float rinv_s[64];
    __shared__ unsigned cm_u[MEM];

    int tid = threadIdx.x, wid = tid >> 5;
    if (tid < 32) cnts[tid] = 0.f;
    if (tid < MEM) cm_u[tid] = 0u;

    {
        const float4* src = (const float4*)g_cacheTf;
        float4* dst = (float4*)CtF;
        for (int id = tid; id < 4096; id += 256) dst[id] = src[id];
    }

    float cmreg[MEM];
    #pragma unroll
    for (int m = 0; m < MEM; m++) cmreg[m] = -1e30f;

    wmma::fragment<wmma::accumulator, 16, 16, 8, float> acc[2][4];
    #pragma unroll
    for (int i = 0; i < 2; i++)
        #pragma unroll
        for (int j = 0; j < 4; j++) wmma::fill_fragment(acc[i][j], 0.f);

    const float4* i4 = (const float4*)img;
    for (int tile = blockIdx.x; tile < 2048; tile += gridDim.x) {
        int base = tile * 64;
        for (int id = tid; id < 64 * 128; id += 256) {
            int r = id >> 7, c = id & 127;
            *((float4*)&Bimg[r * 520 + c * 4]) = i4[(size_t)(base + r) * 128 + c];
        }
        for (int id = tid; id < 32 * 72; id += 256) Aw[id] = 0.f;
        __syncthreads();

        // row sumsq: 4 threads per row
        {
            int r = tid >> 2, q = tid & 3;
            const float4* row = (const float4*)&Bimg[r * 520];
            float ss = 0.f;
            #pragma unroll
            for (int t = 0; t < 32; t++) {
                float4 v = row[q * 32 + t];
                ss += v.x * v.x + v.y * v.y + v.z * v.z + v.w * v.w;
            }
            ss += __shfl_xor_sync(0xffffffffu, ss, 1);
            ss += __shfl_xor_sync(0xffffffffu, ss, 2);
            if (q == 0) rinv_s[r] = rsqrtf(ss);
        }

        // score MMA (tf32 big+small, near-fp32 accurate — argmax must match reference):
        // S[64x32] = Bimg @ CtF
        {
            int rowt = wid >> 1, colt = wid & 1;
            wmma::fragment<wmma::accumulator, 16, 16, 8, float> sacc;
            wmma::fill_fragment(sacc, 0.f);
            for (int k0 = 0; k0 < 512; k0 += 8) {
                wmma::fragment<wmma::matrix_a, 16, 16, 8, wmma::precision::tf32, wmma::row_major> ab, as;
                wmma::fragment<wmma::matrix_b, 16, 16, 8, wmma::precision::tf32, wmma::row_major> bb, bs;
                wmma::load_matrix_sync(ab, Bimg + (rowt * 16) * 520 + k0, 520);
                wmma::load_matrix_sync(bb, CtF + k0 * 32 + colt * 16, 32);
                #pragma unroll
                for (int t = 0; t < ab.num_elements; t++) {
                    float x = ab.x[t];
                    float big = wmma::__float_to_tf32(x);
                    ab.x[t] = big;
                    as.x[t] = wmma::__float_to_tf32(x - big);
                }
                #pragma unroll
                for (int t = 0; t < bb.num_elements; t++) {
                    float x = bb.x[t];
                    float big = wmma::__float_to_tf32(x);
                    bb.x[t] = big;
                    bs.x[t] = wmma::__float_to_tf32(x - big);
                }
                wmma::mma_sync(sacc, ab, bs, sacc);
                wmma::mma_sync(sacc, as, bb, sacc);
                wmma::mma_sync(sacc, ab, bb, sacc);
            }
            wmma::store_matrix_sync(Ssm + (rowt * 16) * 36 + colt * 16, sacc, 36,
                                    wmma::mem_row_major);
        }
        __syncthreads();

        // argmax + one-hot weight (unnormalized: exp(s)*rinv; colmax applied in k_update)
        if (tid < 64) {
            float rv = rinv_s[tid];
            float best = -1e30f; int bi = 0;
            #pragma unroll
            for (int m = 0; m < MEM; m++) {
                float v = Ssm[tid * 36 + m] * rv;
                cmreg[m] = fmaxf(cmreg[m], v);
                if (v > best) { best = v; bi = m; }
            }
            Aw[bi * 72 + tid] = __expf(best) * rv;
            atomicAdd(&cnts[bi], 1.f);
        }
        __syncthreads();

        // scatter MMA: acc += Aw(one-hot) @ Bimg
        for (int ks = 0; ks < 8; ks++) {
            int k0 = ks * 8;
            wmma::fragment<wmma::matrix_a, 16, 16, 8, wmma::precision::tf32, wmma::row_major> af[2];
            wmma::fragment<wmma::matrix_b, 16, 16, 8, wmma::precision::tf32, wmma::row_major> bf[4];
            #pragma unroll
            for (int i = 0; i < 2; i++) {
                wmma::load_matrix_sync(af[i], Aw + (i * 16) * 72 + k0, 72);
                #pragma unroll
                for (int t = 0; t < af[i].num_elements; t++)
                    af[i].x[t] = wmma::__float_to_tf32(af[i].x[t]);
            }
            #pragma unroll
            for (int j = 0; j < 4; j++) {
                wmma::load_matrix_sync(bf[j], Bimg + k0 * 520 + wid * 64 + j * 16, 520);
                #pragma unroll
                for (int t = 0; t < bf[j].num_elements; t++)
                    bf[j].x[t] = wmma::__float_to_tf32(bf[j].x[t]);
            }
            #pragma unroll
            for (int i = 0; i < 2; i++)
                #pragma unroll
                for (int j = 0; j < 4; j++)
                    wmma::mma_sync(acc[i][j], af[i], bf[j], acc[i][j]);
        }
        __syncthreads();
    }

    #pragma unroll
    for (int i = 0; i < 2; i++)
        #pragma unroll
        for (int j = 0; j < 4; j++)
            wmma::store_matrix_sync(g_segp + (size_t)blockIdx.x * 16384 + (i * 16) * 512 +
                                    wid * 64 + j * 16, acc[i][j], 512, wmma::mem_row_major);
    if (tid < 32) g_cntp[blockIdx.x * 32 + tid] = cnts[tid];

    if (tid < 64) {
        #pragma unroll
        for (int m = 0; m < MEM; m++) atomicMax(&cm_u[m], f2o(cmreg[m]));
    }
    __syncthreads();
    if (tid < MEM) atomicMax(&g_colmax[tid], cm_u[tid]);
}

// ---------------- cache EMA update + normalize (applies exp(-colmax)) ----------------
__global__ void k_update(const float* __restrict__ cache, float* __restrict__ out) {
    int m = blockIdx.x, d = threadIdx.x;
    float cnt = 0.f;
    for (int b = 0; b < WBLK; b++) cnt += g_cntp[b * 32 + m];
    float s = 0.f;
    for (int b = 0; b < WBLK; b++) s += g_segp[(size_t)b * 16384 + m * 512 + d];
    float cm = o2f(g_colmax[m]);
    s *= __expf(-cm);
    float cv = cache[m * DIM + d];
    float u = (cnt > 0.f) ? (MOM * cv + (1.f - MOM) * s) : cv;
    float v = u * u;
    v = wredsum(v);
    __shared__ float red[16];
    __shared__ float tot;
    if ((threadIdx.x & 31) == 0) red[threadIdx.x >> 5] = v;
    __syncthreads();
    if (threadIdx.x < 32) {
        float t = (threadIdx.x < 16) ? red[threadIdx.x] : 0.f;
        t = wredsum(t);
        if (threadIdx.x == 0) tot = t;
    }
    __syncthreads();
    float inv = 1.f / fmaxf(sqrtf(tot), 1e-12f);
    out[(size_t)N_TOK * DIM + 1 + m * DIM + d] = u * inv;
}

// ---------------- launch ----------------
extern "C" void kernel_launch(void* const* d_in, const int* in_sizes, int n_in,
                              void* d_out, int out_size) {
    const float* text  = (const float*)d_in[0];
    const float* img   = (const float*)d_in[1];
    const float* W     = (const float*)d_in[2];
    const float* cache = (const float*)d_in[3];
    float* out = (float*)d_out;

    const int FUSED_SMEM = 141312 + 69632 + 512;                 // 211456
    const int WRITE_SMEM = 133120 + 65536 + 9216 + 9216;         // 217088

    cudaFuncSetAttribute(k_fused, cudaFuncAttributeMaxDynamicSharedMemorySize, FUSED_SMEM);
    cudaFuncSetAttribute(k_write, cudaFuncAttributeMaxDynamicSharedMemorySize, WRITE_SMEM);

    k_acw2<<<MEM, 256>>>(W, cache);                     // launch 1
    k_prepB<<<(544 * 512 + 255) / 256, 256>>>(W);       // launch 2
    k_prepC<<<(512 * 32 + 255) / 256, 256>>>(cache);    // launch 3
    k_fused<<<1024, 256, FUSED_SMEM>>>(text, out);      // launch 4  <- ncu samples this
    k_write<<<WBLK, 256, WRITE_SMEM>>>(img);            // launch 5
    k_loss2<<<1, 256>>>(out);                           // launch 6
    k_update<<<MEM, 512>>>(cache, out);                 // launch 7
}

// round 12
// speedup vs baseline: 1.4448x; 1.4067x over previous
#include <cuda_runtime.h>
#include <cuda_bf16.h>
#include <mma.h>

#define N_TOK 131072
#define DIM   512
#define MEM   25
#define ALPHA 0.2f
#define MOM   0.8f
#define WBLK  148

using namespace nvcuda;

// ---------------- scratch (device globals; no allocation) ----------------
__device__ __nv_bfloat16 g_Bbig[544 * 512];     // [alpha*W1^T ; alpha*cache@W2^T ; 0] bf16
__device__ __nv_bfloat16 g_cacheT[512 * 32];    // cache^T bf16, padded to 32 slots
__device__ float    g_cacheTf[512 * 32];        // cache^T fp32
__device__ float    g_ACW2[MEM * DIM];          // ALPHA * cache @ W2^T (fp32)
__device__ unsigned g_colmax[MEM];
__device__ float    g_segp[WBLK * 32 * 512];    // per-block scatter partials (unnormalized)
__device__ float    g_cntp[WBLK * 32];
__device__ float    g_losspart[1024];

__device__ __forceinline__ unsigned f2o(float f) {
    unsigned u = __float_as_uint(f);
    return (u & 0x80000000u) ? ~u : (u | 0x80000000u);
}
__device__ __forceinline__ float o2f(unsigned u) {
    return __uint_as_float((u & 0x80000000u) ? (u & 0x7FFFFFFFu) : ~u);
}
__device__ __forceinline__ float wredsum(float v) {
    v += __shfl_xor_sync(0xffffffffu, v, 16);
    v += __shfl_xor_sync(0xffffffffu, v, 8);
    v += __shfl_xor_sync(0xffffffffu, v, 4);
    v += __shfl_xor_sync(0xffffffffu, v, 2);
    v += __shfl_xor_sync(0xffffffffu, v, 1);
    return v;
}
__device__ __forceinline__ float wredmax(float v) {
    v = fmaxf(v, __shfl_xor_sync(0xffffffffu, v, 16));
    v = fmaxf(v, __shfl_xor_sync(0xffffffffu, v, 8));
    v = fmaxf(v, __shfl_xor_sync(0xffffffffu, v, 4));
    v = fmaxf(v, __shfl_xor_sync(0xffffffffu, v, 2));
    v = fmaxf(v, __shfl_xor_sync(0xffffffffu, v, 1));
    return v;
}

// ---------------- launch 1: ACW2 + colmax init ----------------
__global__ void k_acw2(const float* __restrict__ W, const float* __restrict__ cache) {
    __shared__ float cs[DIM];
    int m = blockIdx.x;
    if (blockIdx.x == 0 && threadIdx.x < MEM) g_colmax[threadIdx.x] = 0u;
    for (int id = threadIdx.x; id < DIM; id += blockDim.x) cs[id] = cache[m * DIM + id];
    __syncthreads();
    int lane = threadIdx.x & 31, wid = threadIdx.x >> 5;
    for (int j = wid * 64; j < wid * 64 + 64; j++) {
        float d = 0.f;
        #pragma unroll
        for (int t = 0; t < 16; t++) {
            int k = lane + 32 * t;
            d += cs[k] * W[(size_t)j * 1024 + 512 + k];
        }
        d = wredsum(d);
        if (lane == 0) g_ACW2[m * DIM + j] = ALPHA * d;
    }
}

// ---------------- launch 2: Bbig build ----------------
__global__ void k_prepB(const float* __restrict__ W) {
    int id = blockIdx.x * 256 + threadIdx.x;
    if (id >= 544 * 512) return;
    int r = id >> 9, o = id & 511;
    float v;
    if (r < 512)            v = ALPHA * W[(size_t)o * 1024 + r];
    else if (r < 512 + MEM) v = g_ACW2[(r - 512) * 512 + o];
    else                    v = 0.f;
    g_Bbig[id] = __float2bfloat16(v);
}

// ---------------- launch 3: cache^T prep ----------------
__global__ void k_prepC(const float* __restrict__ cache) {
    int id = blockIdx.x * 256 + threadIdx.x;
    if (id >= 512 * 32) return;
    int k = id >> 5, m = id & 31;
    float v = (m < MEM) ? cache[m * DIM + k] : 0.f;
    g_cacheT[id] = __float2bfloat16(v);
    g_cacheTf[id] = v;
}

// ---------------- launch 4 (profiled): norm + score + softmax + GEMM + residual + loss ----------------
// smem: A bf16 [128][552] 141312 | B region 78336:
//   Bs bf16 [544][72] (stride 144B, conflict-free) / {Ct bf16[512][40], Ssm f32[128][36]} / Cs f32[128][68]
// | rowss f32[128]
__global__ void __launch_bounds__(256) k_fused(const float* __restrict__ text,
                                               float* __restrict__ out) {
    extern __shared__ unsigned char smem_raw[];
    __nv_bfloat16* A  = (__nv_bfloat16*)smem_raw;
    unsigned char* Br = smem_raw + 141312;
    __nv_bfloat16* Bs = (__nv_bfloat16*)Br;                 // [544][72]
    __nv_bfloat16* Ct = (__nv_bfloat16*)Br;                 // [512][40]
    float* Ssm   = (float*)(Br + 40960);                    // [128][36]
    float* Cs    = (float*)Br;                              // [128][68]
    float* rowss = (float*)(smem_raw + 141312 + 78336);

    int tid = threadIdx.x, lane = tid & 31, wid = tid >> 5;
    int row0 = blockIdx.x * 128;
    const float4* t4 = (const float4*)text;

    // stage 1: text -> bf16 tile + row sumsq (warp owns 16 rows, 1 wredsum/row)
    #pragma unroll 4
    for (int rr = 0; rr < 16; rr++) {
        int r = wid * 16 + rr;
        float ss = 0.f;
        #pragma unroll
        for (int t = 0; t < 4; t++) {
            int c = lane + 32 * t;
            float4 v = t4[(size_t)(row0 + r) * 128 + c];
            ss += v.x * v.x + v.y * v.y + v.z * v.z + v.w * v.w;
            __nv_bfloat162* dst = (__nv_bfloat162*)(A + r * 552 + c * 4);
            dst[0] = __floats2bfloat162_rn(v.x, v.y);
            dst[1] = __floats2bfloat162_rn(v.z, v.w);
        }
        ss = wredsum(ss);
        if (lane == 0) rowss[r] = ss;
    }
    for (int id = tid; id < 128 * 40; id += 256) {
        int r = id / 40, c = 512 + id % 40;
        A[r * 552 + c] = __float2bfloat16(0.f);
    }
    // load cacheT bf16 into padded [512][40]  (bf16 row = 32 bf16 = 4 float4s)
    for (int id = tid; id < 512 * 4; id += 256) {
        int k = id >> 2, g = id & 3;
        ((float4*)(Ct + k * 40))[g] = ((const float4*)g_cacheT)[k * 4 + g];
    }
    __syncthreads();

    // stage 2: score MMA  S[128x32] = A(text) @ cacheT
    {
        wmma::fragment<wmma::accumulator, 16, 16, 16, float> sacc[2];
        wmma::fill_fragment(sacc[0], 0.f);
        wmma::fill_fragment(sacc[1], 0.f);
        for (int k0 = 0; k0 < 512; k0 += 16) {
            wmma::fragment<wmma::matrix_a, 16, 16, 16, __nv_bfloat16, wmma::row_major> af;
            wmma::load_matrix_sync(af, A + (wid * 16) * 552 + k0, 552);
            #pragma unroll
            for (int j = 0; j < 2; j++) {
                wmma::fragment<wmma::matrix_b, 16, 16, 16, __nv_bfloat16, wmma::row_major> bf;
                wmma::load_matrix_sync(bf, Ct + k0 * 40 + j * 16, 40);
                wmma::mma_sync(sacc[j], af, bf, sacc[j]);
            }
        }
        wmma::store_matrix_sync(Ssm + (wid * 16) * 36, sacc[0], 36, wmma::mem_row_major);
        wmma::store_matrix_sync(Ssm + (wid * 16) * 36 + 16, sacc[1], 36, wmma::mem_row_major);
    }
    __syncthreads();

    // stage 3: softmax -> p into A cols 512..536
    for (int rr = 0; rr < 16; rr++) {
        int r = wid * 16 + rr;
        float rinv = 1.f / fmaxf(sqrtf(rowss[r]), 1e-12f);
        float s = (lane < MEM) ? Ssm[r * 36 + lane] * rinv : -1e30f;
        float mx = wredmax(s);
        float e = (lane < MEM) ? expf(s - mx) : 0.f;
        float sum = wredsum(e);
        if (lane < MEM) A[r * 552 + 512 + lane] = __float2bfloat16(e / sum);
    }
    __syncthreads();

    // stage 4: out = ([text|p] @ Bbig) + text, smem-staged epilogue
    int wr = wid & 3, wc = wid >> 2;
    for (int cb = 0; cb < 8; cb++) {
        int col0 = cb * 64;
        for (int id = tid; id < 544 * 8; id += 256) {
            int r = id >> 3, g = id & 7;
            ((float4*)(Bs + r * 72))[g] = ((const float4*)g_Bbig)[r * 64 + (col0 >> 3) + g];
        }
        __syncthreads();
        wmma::fragment<wmma::accumulator, 16, 16, 16, float> acc[2][2];
        #pragma unroll
        for (int i = 0; i < 2; i++)
            #pragma unroll
            for (int j = 0; j < 2; j++) wmma::fill_fragment(acc[i][j], 0.f);
        for (int k0 = 0; k0 < 544; k0 += 16) {
            wmma::fragment<wmma::matrix_a, 16, 16, 16, __nv_bfloat16, wmma::row_major> af[2];
            wmma::fragment<wmma::matrix_b, 16, 16, 16, __nv_bfloat16, wmma::row_major> bf[2];
            #pragma unroll
            for (int i = 0; i < 2; i++)
                wmma::load_matrix_sync(af[i], A + (wr * 32 + i * 16) * 552 + k0, 552);
            #pragma unroll
            for (int j = 0; j < 2; j++)
                wmma::load_matrix_sync(bf[j], Bs + k0 * 72 + wc * 32 + j * 16, 72);
            #pragma unroll
            for (int i = 0; i < 2; i++)
                #pragma unroll
                for (int j = 0; j < 2; j++)
                    wmma::mma_sync(acc[i][j], af[i], bf[j], acc[i][j]);
        }
        __syncthreads();   // done reading Bs before Cs overwrites it
        #pragma unroll
        for (int i = 0; i < 2; i++)
            #pragma unroll
            for (int j = 0; j < 2; j++)
                wmma::store_matrix_sync(Cs + (wr * 32 + i * 16) * 68 + wc * 32 + j * 16,
                                        acc[i][j], 68, wmma::mem_row_major);
        __syncthreads();
        for (int it = 0; it < 8; it++) {
            int id = it * 256 + tid;
            int r = id >> 4, q = id & 15;
            float4 v = *((float4*)&Cs[r * 68 + q * 4]);
            float4 t = t4[(size_t)(row0 + r) * 128 + (col0 >> 2) + q];
            v.x += t.x; v.y += t.y; v.z += t.z; v.w += t.w;
            ((float4*)out)[(size_t)(row0 + r) * 128 + (col0 >> 2) + q] = v;
        }
        __syncthreads();
    }

    // stage 5: loss partial over this block's 128 rows (out tile is L2-hot)
    {
        const float4* o4 = (const float4*)out;
        float accum = 0.f;
        #pragma unroll
        for (int rr = 0; rr < 16; rr++) {
            int i = row0 + wid * 16 + rr;
            float4 tf[4]; float ss = 0.f;
            #pragma unroll
            for (int t = 0; t < 4; t++) {
                tf[t] = o4[(size_t)i * 128 + lane + 32 * t];
                ss += tf[t].x * tf[t].x + tf[t].y * tf[t].y + tf[t].z * tf[t].z + tf[t].w * tf[t].w;
            }
            ss = wredsum(ss);
            float inv = 1.f / fmaxf(sqrtf(ss), 1e-12f);
            float sa = 0.f;
            #pragma unroll
            for (int t = 0; t < 4; t++) {
                float4 x = t4[(size_t)i * 128 + lane + 32 * t];
                sa += fabsf(tf[t].x * inv - x.x) + fabsf(tf[t].y * inv - x.y) +
                      fabsf(tf[t].z * inv - x.z) + fabsf(tf[t].w * inv - x.w);
            }
            accum += wredsum(sa);
        }
        __shared__ float ws[8];
        if (lane == 0) ws[wid] = accum;
        __syncthreads();
        if (tid == 0) {
            float s = 0.f;
            #pragma unroll
            for (int w = 0; w < 8; w++) s += ws[w];
            g_losspart[blockIdx.x] = s;
        }
    }
}

__global__ void k_loss2(float* __restrict__ out) {
    __shared__ float sh[256];
    int tid = threadIdx.x;
    float s = 0.f;
    for (int id = tid; id < 1024; id += 256) s += g_losspart[id];
    sh[tid] = s;
    __syncthreads();
    for (int off = 128; off > 0; off >>= 1) {
        if (tid < off) sh[tid] += sh[tid + off];
        __syncthreads();
    }
    if (tid == 0) out[(size_t)N_TOK * DIM] = sh[0] * (1.0f / 67108864.0f);
}

// ---------------- fused write: img attention (tf32 big+small split) + one-hot scatter MMA ----------------
// smem: Bimg f32[64][524] 134144 | CtF f32[512][36] 73728 | Aw f32[32][76] 9728 | Ssm f32[64][36] 9216
__global__ void __launch_bounds__(256) k_write(const float* __restrict__ img) {
    extern __shared__ unsigned char sraw[];
    float* Bimg = (float*)sraw;                             // [64][524]
    float* CtF  = (float*)(sraw + 134144);                  // [512][36]
    float* Aw   = (float*)(sraw + 134144 + 73728);          // [32][76]
    float* Ssm  = (float*)(sraw + 134144 + 73728 + 9728);   // [64][36]
    __shared__ float cnts[32];
    __shared__ float rinv_s[64];
    __shared__ unsigned cm_u[MEM];

    int tid = threadIdx.x, lane = tid & 31, wid = tid >> 5;
    if (tid < 32) cnts[tid] = 0.f;
    if (tid < MEM) cm_u[tid] = 0u;

    // load cache^T fp32 into padded [512][36]  (fp32 row = 32 floats = 8 float4s)
    for (int id = tid; id < 512 * 8; id += 256) {
        int k = id >> 3, g = id & 7;
        ((float4*)(CtF + k * 36))[g] = ((const float4*)g_cacheTf)[k * 8 + g];
    }

    float cmreg[MEM];
    #pragma unroll
    for (int m = 0; m < MEM; m++) cmreg[m] = -1e30f;

    wmma::fragment<wmma::accumulator, 16, 16, 8, float> acc[2][4];
    #pragma unroll
    for (int i = 0; i < 2; i++)
        #pragma unroll
        for (int j = 0; j < 4; j++) wmma::fill_fragment(acc[i][j], 0.f);

    const float4* i4 = (const float4*)img;
    for (int tile = blockIdx.x; tile < 2048; tile += gridDim.x) {
        int base = tile * 64;
        // load tile + fused row sumsq (warp owns 8 rows)
        #pragma unroll 2
        for (int rr = 0; rr < 8; rr++) {
            int r = wid * 8 + rr;
            float ss = 0.f;
            #pragma unroll
            for (int t = 0; t < 4; t++) {
                int c = lane + 32 * t;
                float4 v = i4[(size_t)(base + r) * 128 + c];
                *((float4*)&Bimg[r * 524 + c * 4]) = v;
                ss += v.x * v.x + v.y * v.y + v.z * v.z + v.w * v.w;
            }
            ss = wredsum(ss);
            if (lane == 0) rinv_s[r] = rsqrtf(ss);
        }
        for (int id = tid; id < 32 * 76; id += 256) Aw[id] = 0.f;
        __syncthreads();

        // score MMA (tf32 big+small, near-fp32 accurate — argmax must match reference):
        // S[64x32] = Bimg @ CtF
        {
            int rowt = wid >> 1, colt = wid & 1;
            wmma::fragment<wmma::accumulator, 16, 16, 8, float> sacc;
            wmma::fill_fragment(sacc, 0.f);
            for (int k0 = 0; k0 < 512; k0 += 8) {
                wmma::fragment<wmma::matrix_a, 16, 16, 8, wmma::precision::tf32, wmma::row_major> ab, as;
                wmma::fragment<wmma::matrix_b, 16, 16, 8, wmma::precision::tf32, wmma::row_major> bb, bs;
                wmma::load_matrix_sync(ab, Bimg + (rowt * 16) * 524 + k0, 524);
                wmma::load_matrix_sync(bb, CtF + k0 * 36 + colt * 16, 36);
                #pragma unroll
                for (int t = 0; t < ab.num_elements; t++) {
                    float x = ab.x[t];
                    float big = wmma::__float_to_tf32(x);
                    ab.x[t] = big;
                    as.x[t] = wmma::__float_to_tf32(x - big);
                }
                #pragma unroll
                for (int t = 0; t < bb.num_elements; t++) {
                    float x = bb.x[t];
                    float big = wmma::__float_to_tf32(x);
                    bb.x[t] = big;
                    bs.x[t] = wmma::__float_to_tf32(x - big);
                }
                wmma::mma_sync(sacc, ab, bs, sacc);
                wmma::mma_sync(sacc, as, bb, sacc);
                wmma::mma_sync(sacc, ab, bb, sacc);
            }
            wmma::store_matrix_sync(Ssm + (rowt * 16) * 36 + colt * 16, sacc, 36,
                                    wmma::mem_row_major);
        }
        __syncthreads();

        // argmax + one-hot weight (unnormalized: exp(s)*rinv; colmax applied in k_update)
        if (tid < 64) {
            float rv = rinv_s[tid];
            float best = -1e30f; int bi = 0;
            #pragma unroll
            for (int m = 0; m < MEM; m++) {
                float v = Ssm[tid * 36 + m] * rv;
                cmreg[m] = fmaxf(cmreg[m], v);
                if (v > best) { best = v; bi = m; }
            }
            Aw[bi * 76 + tid] = __expf(best) * rv;
            atomicAdd(&cnts[bi], 1.f);
        }
        __syncthreads();

        // scatter MMA: acc += Aw(one-hot) @ Bimg
        for (int ks = 0; ks < 8; ks++) {
            int k0 = ks * 8;
            wmma::fragment<wmma::matrix_a, 16, 16, 8, wmma::precision::tf32, wmma::row_major> af[2];
            wmma::fragment<wmma::matrix_b, 16, 16, 8, wmma::precision::tf32, wmma::row_major> bf[4];
            #pragma unroll
            for (int i = 0; i < 2; i++) {
                wmma::load_matrix_sync(af[i], Aw + (i * 16) * 76 + k0, 76);
                #pragma unroll
                for (int t = 0; t < af[i].num_elements; t++)
                    af[i].x[t] = wmma::__float_to_tf32(af[i].x[t]);
            }
            #pragma unroll
            for (int j = 0; j < 4; j++) {
                wmma::load_matrix_sync(bf[j], Bimg + k0 * 524 + wid * 64 + j * 16, 524);
                #pragma unroll
                for (int t = 0; t < bf[j].num_elements; t++)
                    bf[j].x[t] = wmma::__float_to_tf32(bf[j].x[t]);
            }
            #pragma unroll
            for (int i = 0; i < 2; i++)
                #pragma unroll
                for (int j = 0; j < 4; j++)
                    wmma::mma_sync(acc[i][j], af[i], bf[j], acc[i][j]);
        }
        __syncthreads();
    }

    #pragma unroll
    for (int i = 0; i < 2; i++)
        #pragma unroll
        for (int j = 0; j < 4; j++)
            wmma::store_matrix_sync(g_segp + (size_t)blockIdx.x * 16384 + (i * 16) * 512 +
                                    wid * 64 + j * 16, acc[i][j], 512, wmma::mem_row_major);
    if (tid < 32) g_cntp[blockIdx.x * 32 + tid] = cnts[tid];

    if (tid < 64) {
        #pragma unroll
        for (int m = 0; m < MEM; m++) atomicMax(&cm_u[m], f2o(cmreg[m]));
    }
    __syncthreads();
    if (tid < MEM) atomicMax(&g_colmax[tid], cm_u[tid]);
}

// ---------------- cache EMA update + normalize (applies exp(-colmax)) ----------------
__global__ void k_update(const float* __restrict__ cache, float* __restrict__ out) {
    int m = blockIdx.x, d = threadIdx.x;
    float cnt = 0.f;
    for (int b = 0; b < WBLK; b++) cnt += g_cntp[b * 32 + m];
    float s = 0.f;
    for (int b = 0; b < WBLK; b++) s += g_segp[(size_t)b * 16384 + m * 512 + d];
    float cm = o2f(g_colmax[m]);
    s *= __expf(-cm);
    float cv = cache[m * DIM + d];
    float u = (cnt > 0.f) ? (MOM * cv + (1.f - MOM) * s) : cv;
    float v = u * u;
    v = wredsum(v);
    __shared__ float red[16];
    __shared__ float tot;
    if ((threadIdx.x & 31) == 0) red[threadIdx.x >> 5] = v;
    __syncthreads();
    if (threadIdx.x < 32) {
        float t = (threadIdx.x < 16) ? red[threadIdx.x] : 0.f;
        t = wredsum(t);
        if (threadIdx.x == 0) tot = t;
    }
    __syncthreads();
    float inv = 1.f / fmaxf(sqrtf(tot), 1e-12f);
    out[(size_t)N_TOK * DIM + 1 + m * DIM + d] = u * inv;
}

// ---------------- launch ----------------
extern "C" void kernel_launch(void* const* d_in, const int* in_sizes, int n_in,
                              void* d_out, int out_size) {
    const float* text  = (const float*)d_in[0];
    const float* img   = (const float*)d_in[1];
    const float* W     = (const float*)d_in[2];
    const float* cache = (const float*)d_in[3];
    float* out = (float*)d_out;

    const int FUSED_SMEM = 141312 + 78336 + 512;                 // 220160
    const int WRITE_SMEM = 134144 + 73728 + 9728 + 9216;         // 226816

    cudaFuncSetAttribute(k_fused, cudaFuncAttributeMaxDynamicSharedMemorySize, FUSED_SMEM);
    cudaFuncSetAttribute(k_write, cudaFuncAttributeMaxDynamicSharedMemorySize, WRITE_SMEM);

    k_acw2<<<MEM, 256>>>(W, cache);                     // launch 1
    k_prepB<<<(544 * 512 + 255) / 256, 256>>>(W);       // launch 2
    k_prepC<<<(512 * 32 + 255) / 256, 256>>>(cache);    // launch 3
    k_fused<<<1024, 256, FUSED_SMEM>>>(text, out);      // launch 4  <- ncu samples this
    k_write<<<WBLK, 256, WRITE_SMEM>>>(img);            // launch 5
    k_loss2<<<1, 256>>>(out);                           // launch 6
    k_update<<<MEM, 512>>>(cache, out);                 // launch 7
}

// round 15
// speedup vs baseline: 1.4505x; 1.0040x over previous
#include <cuda_runtime.h>
#include <cuda_bf16.h>
#include <mma.h>

#define N_TOK 131072
#define DIM   512
#define MEM   25
#define ALPHA 0.2f
#define MOM   0.8f
#define WBLK  148

using namespace nvcuda;

// ---------------- scratch (device globals; no allocation) ----------------
__device__ __nv_bfloat16 g_Bbig[544 * 512];
__device__ __nv_bfloat16 g_cacheT[512 * 32];
__device__ float    g_cacheTf[512 * 32];
__device__ float    g_ACW2[MEM * DIM];
__device__ unsigned g_colmax[MEM];
__device__ float    g_segp[WBLK * 32 * 512];
__device__ float    g_cntp[WBLK * 32];
__device__ float    g_losspart[1024];

__device__ __forceinline__ unsigned f2o(float f) {
    unsigned u = __float_as_uint(f);
    return (u & 0x80000000u) ? ~u : (u | 0x80000000u);
}
__device__ __forceinline__ float o2f(unsigned u) {
    return __uint_as_float((u & 0x80000000u) ? (u & 0x7FFFFFFFu) : ~u);
}
__device__ __forceinline__ float wredsum(float v) {
    v += __shfl_xor_sync(0xffffffffu, v, 16);
    v += __shfl_xor_sync(0xffffffffu, v, 8);
    v += __shfl_xor_sync(0xffffffffu, v, 4);
    v += __shfl_xor_sync(0xffffffffu, v, 2);
    v += __shfl_xor_sync(0xffffffffu, v, 1);
    return v;
}
__device__ __forceinline__ float wredmax(float v) {
    v = fmaxf(v, __shfl_xor_sync(0xffffffffu, v, 16));
    v = fmaxf(v, __shfl_xor_sync(0xffffffffu, v, 8));
    v = fmaxf(v, __shfl_xor_sync(0xffffffffu, v, 4));
    v = fmaxf(v, __shfl_xor_sync(0xffffffffu, v, 2));
    v = fmaxf(v, __shfl_xor_sync(0xffffffffu, v, 1));
    return v;
}

// ---------------- launch 1: ACW2 + colmax init ----------------
__global__ void k_acw2(const float* __restrict__ W, const float* __restrict__ cache) {
    __shared__ float cs[DIM];
    int m = blockIdx.x;
    if (blockIdx.x == 0 && threadIdx.x < MEM) g_colmax[threadIdx.x] = 0u;
    for (int id = threadIdx.x; id < DIM; id += blockDim.x) cs[id] = cache[m * DIM + id];
    __syncthreads();
    int lane = threadIdx.x & 31, wid = threadIdx.x >> 5;
    for (int j = wid * 64; j < wid * 64 + 64; j++) {
        float d = 0.f;
        #pragma unroll
        for (int t = 0; t < 16; t++) {
            int k = lane + 32 * t;
            d += cs[k] * W[(size_t)j * 1024 + 512 + k];
        }
        d = wredsum(d);
        if (lane == 0) g_ACW2[m * DIM + j] = ALPHA * d;
    }
}

// ---------------- launch 2: Bbig ----------------
__global__ void k_prepB(const float* __restrict__ W) {
    int id = blockIdx.x * 256 + threadIdx.x;
    if (id >= 544 * 512) return;
    int r = id >> 9, o = id & 511;
    float v;
    if (r < 512)            v = ALPHA * W[(size_t)o * 1024 + r];
    else if (r < 512 + MEM) v = g_ACW2[(r - 512) * 512 + o];
    else                    v = 0.f;
    g_Bbig[id] = __float2bfloat16(v);
}

// ---------------- launch 3: cache^T ----------------
__global__ void k_prepC(const float* __restrict__ cache) {
    int id = blockIdx.x * 256 + threadIdx.x;
    if (id >= 512 * 32) return;
    int k = id >> 5, m = id & 31;
    float v = (m < MEM) ? cache[m * DIM + k] : 0.f;
    g_cacheT[id] = __float2bfloat16(v);
    g_cacheTf[id] = v;
}

// ---------------- launch 4 (profiled): 512-thread fused kernel ----------------
// smem: A bf16 [128][552] 141312 | B region 78336 (Bs[544][72] / {Ct[512][40], Ssm[128][36]} / Cs[128][68])
// | rowss f32[128]
__global__ void __launch_bounds__(512) k_fused(const float* __restrict__ text,
                                               float* __restrict__ out) {
    extern __shared__ unsigned char smem_raw[];
    __nv_bfloat16* A  = (__nv_bfloat16*)smem_raw;
    unsigned char* Br = smem_raw + 141312;
    __nv_bfloat16* Bs = (__nv_bfloat16*)Br;                 // [544][72]
    __nv_bfloat16* Ct = (__nv_bfloat16*)Br;                 // [512][40]
    float* Ssm   = (float*)(Br + 40960);                    // [128][36]
    float* Cs    = (float*)Br;                              // [128][68]
    float* rowss = (float*)(smem_raw + 141312 + 78336);

    int tid = threadIdx.x, lane = tid & 31, wid = tid >> 5;   // 16 warps
    int row0 = blockIdx.x * 128;
    const float4* t4 = (const float4*)text;

    // stage 1: text -> bf16 tile + row sumsq (warp owns 8 rows)
    #pragma unroll 4
    for (int rr = 0; rr < 8; rr++) {
        int r = wid * 8 + rr;
        float ss = 0.f;
        #pragma unroll
        for (int t = 0; t < 4; t++) {
            int c = lane + 32 * t;
            float4 v = t4[(size_t)(row0 + r) * 128 + c];
            ss += v.x * v.x + v.y * v.y + v.z * v.z + v.w * v.w;
            __nv_bfloat162* dst = (__nv_bfloat162*)(A + r * 552 + c * 4);
            dst[0] = __floats2bfloat162_rn(v.x, v.y);
            dst[1] = __floats2bfloat162_rn(v.z, v.w);
        }
        ss = wredsum(ss);
        if (lane == 0) rowss[r] = ss;
    }
    for (int id = tid; id < 128 * 40; id += 512) {
        int r = id / 40, c = 512 + id % 40;
        A[r * 552 + c] = __float2bfloat16(0.f);
    }
    for (int id = tid; id < 512 * 4; id += 512) {
        int k = id >> 2, g = id & 3;
        ((float4*)(Ct + k * 40))[g] = ((const float4*)g_cacheT)[k * 4 + g];
    }
    __syncthreads();

    // stage 2: score MMA  S[128x32] = A(text) @ cacheT   (warps 0-7, 16 rows each)
    if (wid < 8) {
        wmma::fragment<wmma::accumulator, 16, 16, 16, float> sacc[2];
        wmma::fill_fragment(sacc[0], 0.f);
        wmma::fill_fragment(sacc[1], 0.f);
        for (int k0 = 0; k0 < 512; k0 += 16) {
            wmma::fragment<wmma::matrix_a, 16, 16, 16, __nv_bfloat16, wmma::row_major> af;
            wmma::load_matrix_sync(af, A + (wid * 16) * 552 + k0, 552);
            #pragma unroll
            for (int j = 0; j < 2; j++) {
                wmma::fragment<wmma::matrix_b, 16, 16, 16, __nv_bfloat16, wmma::row_major> bf;
                wmma::load_matrix_sync(bf, Ct + k0 * 40 + j * 16, 40);
                wmma::mma_sync(sacc[j], af, bf, sacc[j]);
            }
        }
        wmma::store_matrix_sync(Ssm + (wid * 16) * 36, sacc[0], 36, wmma::mem_row_major);
        wmma::store_matrix_sync(Ssm + (wid * 16) * 36 + 16, sacc[1], 36, wmma::mem_row_major);
    }
    __syncthreads();

    // stage 3: softmax -> p into A cols 512..536 (warps 0-7)
    if (wid < 8) {
        for (int rr = 0; rr < 16; rr++) {
            int r = wid * 16 + rr;
            float rinv = 1.f / fmaxf(sqrtf(rowss[r]), 1e-12f);
            float s = (lane < MEM) ? Ssm[r * 36 + lane] * rinv : -1e30f;
            float mx = wredmax(s);
            float e = (lane < MEM) ? expf(s - mx) : 0.f;
            float sum = wredsum(e);
            if (lane < MEM) A[r * 552 + 512 + lane] = __float2bfloat16(e / sum);
        }
    }
    __syncthreads();

    // stage 4: out = ([text|p] @ Bbig) + text; 16 warps as 8 row-tiles x 2 col-tiles
    int wr = wid & 7, wc = wid >> 3;
    for (int cb = 0; cb < 8; cb++) {
        int col0 = cb * 64;
        for (int id = tid; id < 544 * 8; id += 512) {
            int r = id >> 3, g = id & 7;
            ((float4*)(Bs + r * 72))[g] = ((const float4*)g_Bbig)[r * 64 + (col0 >> 3) + g];
        }
        __syncthreads();
        wmma::fragment<wmma::accumulator, 16, 16, 16, float> acc[2];
        wmma::fill_fragment(acc[0], 0.f);
        wmma::fill_fragment(acc[1], 0.f);
        for (int k0 = 0; k0 < 544; k0 += 16) {
            wmma::fragment<wmma::matrix_a, 16, 16, 16, __nv_bfloat16, wmma::row_major> af;
            wmma::fragment<wmma::matrix_b, 16, 16, 16, __nv_bfloat16, wmma::row_major> bf[2];
            wmma::load_matrix_sync(af, A + (wr * 16) * 552 + k0, 552);
            #pragma unroll
            for (int j = 0; j < 2; j++)
                wmma::load_matrix_sync(bf[j], Bs + k0 * 72 + wc * 32 + j * 16, 72);
            #pragma unroll
            for (int j = 0; j < 2; j++)
                wmma::mma_sync(acc[j], af, bf[j], acc[j]);
        }
        __syncthreads();   // done reading Bs before Cs overwrites it
        #pragma unroll
        for (int j = 0; j < 2; j++)
            wmma::store_matrix_sync(Cs + (wr * 16) * 68 + wc * 32 + j * 16,
                                    acc[j], 68, wmma::mem_row_major);
        __syncthreads();
        for (int it = 0; it < 4; it++) {
            int id = it * 512 + tid;
            int r = id >> 4, q = id & 15;
            float4 v = *((float4*)&Cs[r * 68 + q * 4]);
            float4 t = t4[(size_t)(row0 + r) * 128 + (col0 >> 2) + q];
            v.x += t.x; v.y += t.y; v.z += t.z; v.w += t.w;
            ((float4*)out)[(size_t)(row0 + r) * 128 + (col0 >> 2) + q] = v;
        }
        __syncthreads();
    }

    // stage 5: loss partial (warp owns 8 rows; out tile is L2-hot)
    {
        const float4* o4 = (const float4*)out;
        float accum = 0.f;
        #pragma unroll
        for (int rr = 0; rr < 8; rr++) {
            int i = row0 + wid * 8 + rr;
            float4 tf[4]; float ss = 0.f;
            #pragma unroll
            for (int t = 0; t < 4; t++) {
                tf[t] = o4[(size_t)i * 128 + lane + 32 * t];
                ss += tf[t].x * tf[t].x + tf[t].y * tf[t].y + tf[t].z * tf[t].z + tf[t].w * tf[t].w;
            }
            ss = wredsum(ss);
            float inv = 1.f / fmaxf(sqrtf(ss), 1e-12f);
            float sa = 0.f;
            #pragma unroll
            for (int t = 0; t < 4; t++) {
                float4 x = t4[(size_t)i * 128 + lane + 32 * t];
                sa += fabsf(tf[t].x * inv - x.x) + fabsf(tf[t].y * inv - x.y) +
                      fabsf(tf[t].z * inv - x.z) + fabsf(tf[t].w * inv - x.w);
            }
            accum += wredsum(sa);
        }
        __shared__ float ws[16];
        if (lane == 0) ws[wid] = accum;
        __syncthreads();
        if (tid == 0) {
            float s = 0.f;
            #pragma unroll
            for (int w = 0; w < 16; w++) s += ws[w];
            g_losspart[blockIdx.x] = s;
        }
    }
}

__global__ void k_loss2(float* __restrict__ out) {
    __shared__ float sh[256];
    int tid = threadIdx.x;
    float s = 0.f;
    for (int id = tid; id < 1024; id += 256) s += g_losspart[id];
    sh[tid] = s;
    __syncthreads();
    for (int off = 128; off > 0; off >>= 1) {
        if (tid < off) sh[tid] += sh[tid + off];
        __syncthreads();
    }
    if (tid == 0) out[(size_t)N_TOK * DIM] = sh[0] * (1.0f / 67108864.0f);
}

// ---------------- fused write (512 threads): img attention + one-hot scatter MMA ----------------
// smem: Bimg f32[64][524] 134144 | CtF f32[512][36] 73728 | Aw f32[32][76] 9728 | Ssm f32[64][36] 9216
__global__ void __launch_bounds__(512) k_write(const float* __restrict__ img) {
    extern __shared__ unsigned char sraw[];
    float* Bimg = (float*)sraw;                             // [64][524]
    float* CtF  = (float*)(sraw + 134144);                  // [512][36]
    float* Aw   = (float*)(sraw + 134144 + 73728);          // [32][76]
    float* Ssm  = (float*)(sraw + 134144 + 73728 + 9728);   // [64][36]
    __shared__ float cnts[32];
    __shared__ float rinv_s[64];
    __shared__ unsigned cm_u[MEM];

    int tid = threadIdx.x, lane = tid & 31, wid = tid >> 5;   // 16 warps
    if (tid < 32) cnts[tid] = 0.f;
    if (tid < MEM) cm_u[tid] = 0u;

    for (int id = tid; id < 512 * 8; id += 512) {
        int k = id >> 3, g = id & 7;
        ((float4*)(CtF + k * 36))[g] = ((const float4*)g_cacheTf)[k * 8 + g];
    }

    float cmreg[MEM];
    #pragma unroll
    for (int m = 0; m < MEM; m++) cmreg[m] = -1e30f;

    // 16 warps: each owns a 32-col slice of the 512-wide accumulator
    wmma::fragment<wmma::accumulator, 16, 16, 8, float> acc[2][2];
    #pragma unroll
    for (int i = 0; i < 2; i++)
        #pragma unroll
        for (int j = 0; j < 2; j++) wmma::fill_fragment(acc[i][j], 0.f);

    const float4* i4 = (const float4*)img;
    for (int tile = blockIdx.x; tile < 2048; tile += gridDim.x) {
        int base = tile * 64;
        // load tile + fused row sumsq (warp owns 4 rows)
        #pragma unroll
        for (int rr = 0; rr < 4; rr++) {
            int r = wid * 4 + rr;
            float ss = 0.f;
            #pragma unroll
            for (int t = 0; t < 4; t++) {
                int c = lane + 32 * t;
                float4 v = i4[(size_t)(base + r) * 128 + c];
                *((float4*)&Bimg[r * 524 + c * 4]) = v;
                ss += v.x * v.x + v.y * v.y + v.z * v.z + v.w * v.w;
            }
            ss = wredsum(ss);
            if (lane == 0) rinv_s[r] = rsqrtf(ss);
        }
        for (int id = tid; id < 32 * 76; id += 512) Aw[id] = 0.f;
        __syncthreads();

        // score MMA (tf32 big+small, near-fp32): S[64x32] = Bimg @ CtF (warps 0-7)
        if (wid < 8) {
            int rowt = wid >> 1, colt = wid & 1;
            wmma::fragment<wmma::accumulator, 16, 16, 8, float> sacc;
            wmma::fill_fragment(sacc, 0.f);
            for (int k0 = 0; k0 < 512; k0 += 8) {
                wmma::fragment<wmma::matrix_a, 16, 16, 8, wmma::precision::tf32, wmma::row_major> ab, as;
                wmma::fragment<wmma::matrix_b, 16, 16, 8, wmma::precision::tf32, wmma::row_major> bb, bs;
                wmma::load_matrix_sync(ab, Bimg + (rowt * 16) * 524 + k0, 524);
                wmma::load_matrix_sync(bb, CtF + k0 * 36 + colt * 16, 36);
                #pragma unroll
                for (int t = 0; t < ab.num_elements; t++) {
                    float x = ab.x[t];
                    float big = wmma::__float_to_tf32(x);
                    ab.x[t] = big;
                    as.x[t] = wmma::__float_to_tf32(x - big);
                }
                #pragma unroll
                for (int t = 0; t < bb.num_elements; t++) {
                    float x = bb.x[t];
                    float big = wmma::__float_to_tf32(x);
                    bb.x[t] = big;
                    bs.x[t] = wmma::__float_to_tf32(x - big);
                }
                wmma::mma_sync(sacc, ab, bs, sacc);
                wmma::mma_sync(sacc, as, bb, sacc);
                wmma::mma_sync(sacc, ab, bb, sacc);
            }
            wmma::store_matrix_sync(Ssm + (rowt * 16) * 36 + colt * 16, sacc, 36,
                                    wmma::mem_row_major);
        }
        __syncthreads();

        // argmax + one-hot weight (unnormalized; colmax applied in k_update)
        if (tid < 64) {
            float rv = rinv_s[tid];
            float best = -1e30f; int bi = 0;
            #pragma unroll
            for (int m = 0; m < MEM; m++) {
                float v = Ssm[tid * 36 + m] * rv;
                cmreg[m] = fmaxf(cmreg[m], v);
                if (v > best) { best = v; bi = m; }
            }
            Aw[bi * 76 + tid] = __expf(best) * rv;
            atomicAdd(&cnts[bi], 1.f);
        }
        __syncthreads();

        // scatter MMA: acc += Aw(one-hot) @ Bimg  (warp covers cols wid*32..wid*32+31)
        for (int ks = 0; ks < 8; ks++) {
            int k0 = ks * 8;
            wmma::fragment<wmma::matrix_a, 16, 16, 8, wmma::precision::tf32, wmma::row_major> af[2];
            wmma::fragment<wmma::matrix_b, 16, 16, 8, wmma::precision::tf32, wmma::row_major> bf[2];
            #pragma unroll
            for (int i = 0; i < 2; i++) {
                wmma::load_matrix_sync(af[i], Aw + (i * 16) * 76 + k0, 76);
                #pragma unroll
                for (int t = 0; t < af[i].num_elements; t++)
                    af[i].x[t] = wmma::__float_to_tf32(af[i].x[t]);
            }
            #pragma unroll
            for (int j = 0; j < 2; j++) {
                wmma::load_matrix_sync(bf[j], Bimg + k0 * 524 + wid * 32 + j * 16, 524);
                #pragma unroll
                for (int t = 0; t < bf[j].num_elements; t++)
                    bf[j].x[t] = wmma::__float_to_tf32(bf[j].x[t]);
            }
            #pragma unroll
            for (int i = 0; i < 2; i++)
                #pragma unroll
                for (int j = 0; j < 2; j++)
                    wmma::mma_sync(acc[i][j], af[i], bf[j], acc[i][j]);
        }
        __syncthreads();
    }

    #pragma unroll
    for (int i = 0; i < 2; i++)
        #pragma unroll
        for (int j = 0; j < 2; j++)
            wmma::store_matrix_sync(g_segp + (size_t)blockIdx.x * 16384 + (i * 16) * 512 +
                                    wid * 32 + j * 16, acc[i][j], 512, wmma::mem_row_major);
    if (tid < 32) g_cntp[blockIdx.x * 32 + tid] = cnts[tid];

    if (tid < 64) {
        #pragma unroll
        for (int m = 0; m < MEM; m++) atomicMax(&cm_u[m], f2o(cmreg[m]));
    }
    __syncthreads();
    if (tid < MEM) atomicMax(&g_colmax[tid], cm_u[tid]);
}

// ---------------- cache EMA update + normalize ----------------
__global__ void k_update(const float* __restrict__ cache, float* __restrict__ out) {
    int m = blockIdx.x, d = threadIdx.x;
    float cnt = 0.f;
    for (int b = 0; b < WBLK; b++) cnt += g_cntp[b * 32 + m];
    float s = 0.f;
    for (int b = 0; b < WBLK; b++) s += g_segp[(size_t)b * 16384 + m * 512 + d];
    float cm = o2f(g_colmax[m]);
    s *= __expf(-cm);
    float cv = cache[m * DIM + d];
    float u = (cnt > 0.f) ? (MOM * cv + (1.f - MOM) * s) : cv;
    float v = u * u;
    v = wredsum(v);
    __shared__ float red[16];
    __shared__ float tot;
    if ((threadIdx.x & 31) == 0) red[threadIdx.x >> 5] = v;
    __syncthreads();
    if (threadIdx.x < 32) {
        float t = (threadIdx.x < 16) ? red[threadIdx.x] : 0.f;
        t = wredsum(t);
        if (threadIdx.x == 0) tot = t;
    }
    __syncthreads();
    float inv = 1.f / fmaxf(sqrtf(tot), 1e-12f);
    out[(size_t)N_TOK * DIM + 1 + m * DIM + d] = u * inv;
}

// ---------------- launch ----------------
extern "C" void kernel_launch(void* const* d_in, const int* in_sizes, int n_in,
                              void* d_out, int out_size) {
    const float* text  = (const float*)d_in[0];
    const float* img   = (const float*)d_in[1];
    const float* W     = (const float*)d_in[2];
    const float* cache = (const float*)d_in[3];
    float* out = (float*)d_out;

    const int FUSED_SMEM = 141312 + 78336 + 512;                 // 220160
    const int WRITE_SMEM = 134144 + 73728 + 9728 + 9216;         // 226816

    cudaFuncSetAttribute(k_fused, cudaFuncAttributeMaxDynamicSharedMemorySize, FUSED_SMEM);
    cudaFuncSetAttribute(k_write, cudaFuncAttributeMaxDynamicSharedMemorySize, WRITE_SMEM);

    k_acw2<<<MEM, 256>>>(W, cache);                     // launch 1
    k_prepB<<<(544 * 512 + 255) / 256, 256>>>(W);       // launch 2
    k_prepC<<<(512 * 32 + 255) / 256, 256>>>(cache);    // launch 3
    k_fused<<<1024, 512, FUSED_SMEM>>>(text, out);      // launch 4  <- ncu samples this
    k_write<<<WBLK, 512, WRITE_SMEM>>>(img);            // launch 5
    k_loss2<<<1, 256>>>(out);                           // launch 6
    k_update<<<MEM, 512>>>(cache, out);                 // launch 7
}

// round 16
// speedup vs baseline: 1.6617x; 1.1456x over previous
#include <cuda_runtime.h>
#include <cuda_bf16.h>
#include <mma.h>

#define N_TOK 131072
#define DIM   512
#define MEM   25
#define ALPHA 0.2f
#define MOM   0.8f
#define WBLK  148

using namespace nvcuda;

// ---------------- scratch (device globals; no allocation) ----------------
__device__ __nv_bfloat16 g_Bbig[544 * 512];
__device__ __nv_bfloat16 g_cacheT[512 * 32];
__device__ float    g_cacheTf[512 * 32];
__device__ float    g_ACW2[MEM * DIM];
__device__ unsigned g_colmax[MEM];
__device__ float    g_segp[WBLK * 32 * 512];
__device__ float    g_cntp[WBLK * 32];
__device__ float    g_losspart[1024];

__device__ __forceinline__ unsigned f2o(float f) {
    unsigned u = __float_as_uint(f);
    return (u & 0x80000000u) ? ~u : (u | 0x80000000u);
}
__device__ __forceinline__ float o2f(unsigned u) {
    return __uint_as_float((u & 0x80000000u) ? (u & 0x7FFFFFFFu) : ~u);
}
__device__ __forceinline__ float wredsum(float v) {
    v += __shfl_xor_sync(0xffffffffu, v, 16);
    v += __shfl_xor_sync(0xffffffffu, v, 8);
    v += __shfl_xor_sync(0xffffffffu, v, 4);
    v += __shfl_xor_sync(0xffffffffu, v, 2);
    v += __shfl_xor_sync(0xffffffffu, v, 1);
    return v;
}
__device__ __forceinline__ float wredmax(float v) {
    v = fmaxf(v, __shfl_xor_sync(0xffffffffu, v, 16));
    v = fmaxf(v, __shfl_xor_sync(0xffffffffu, v, 8));
    v = fmaxf(v, __shfl_xor_sync(0xffffffffu, v, 4));
    v = fmaxf(v, __shfl_xor_sync(0xffffffffu, v, 2));
    v = fmaxf(v, __shfl_xor_sync(0xffffffffu, v, 1));
    return v;
}

// ---------------- launch 1: ACW2 + colmax init ----------------
__global__ void k_acw2(const float* __restrict__ W, const float* __restrict__ cache) {
    __shared__ float cs[DIM];
    int m = blockIdx.x;
    if (blockIdx.x == 0 && threadIdx.x < MEM) g_colmax[threadIdx.x] = 0u;
    for (int id = threadIdx.x; id < DIM; id += blockDim.x) cs[id] = cache[m * DIM + id];
    __syncthreads();
    int lane = threadIdx.x & 31, wid = threadIdx.x >> 5;
    for (int j = wid * 64; j < wid * 64 + 64; j++) {
        float d = 0.f;
        #pragma unroll
        for (int t = 0; t < 16; t++) {
            int k = lane + 32 * t;
            d += cs[k] * W[(size_t)j * 1024 + 512 + k];
        }
        d = wredsum(d);
        if (lane == 0) g_ACW2[m * DIM + j] = ALPHA * d;
    }
}

// ---------------- launch 2: Bbig ----------------
__global__ void k_prepB(const float* __restrict__ W) {
    int id = blockIdx.x * 256 + threadIdx.x;
    if (id >= 544 * 512) return;
    int r = id >> 9, o = id & 511;
    float v;
    if (r < 512)            v = ALPHA * W[(size_t)o * 1024 + r];
    else if (r < 512 + MEM) v = g_ACW2[(r - 512) * 512 + o];
    else                    v = 0.f;
    g_Bbig[id] = __float2bfloat16(v);
}

// ---------------- launch 3: cache^T ----------------
__global__ void k_prepC(const float* __restrict__ cache) {
    int id = blockIdx.x * 256 + threadIdx.x;
    if (id >= 512 * 32) return;
    int k = id >> 5, m = id & 31;
    float v = (m < MEM) ? cache[m * DIM + k] : 0.f;
    g_cacheT[id] = __float2bfloat16(v);
    g_cacheTf[id] = v;
}

// ---------------- launch 4 (profiled): 512-thread fused kernel ----------------
// smem: A bf16 [128][552] 141312 | B region 78336:
//   stage4: Bs bf16 [272][136] (73984) then Cs f32 [128][132] (67584)
//   stage2: Ct bf16[512][40] (40960) | Ssm f32[128][36] (18432) | Ssm2 f32[128][36] (18432)
// | rowss f32[128]
__global__ void __launch_bounds__(512) k_fused(const float* __restrict__ text,
                                               float* __restrict__ out) {
    extern __shared__ unsigned char smem_raw[];
    __nv_bfloat16* A  = (__nv_bfloat16*)smem_raw;
    unsigned char* Br = smem_raw + 141312;
    __nv_bfloat16* Bs = (__nv_bfloat16*)Br;                 // [272][136]
    __nv_bfloat16* Ct = (__nv_bfloat16*)Br;                 // [512][40]
    float* Ssm   = (float*)(Br + 40960);                    // [128][36]
    float* Ssm2  = (float*)(Br + 59392);                    // [128][36]
    float* Cs    = (float*)Br;                              // [128][132]
    float* rowss = (float*)(smem_raw + 141312 + 78336);

    int tid = threadIdx.x, lane = tid & 31, wid = tid >> 5;   // 16 warps
    int row0 = blockIdx.x * 128;
    const float4* t4 = (const float4*)text;

    // stage 1: text -> bf16 tile + row sumsq (warp owns 8 rows)
    #pragma unroll 4
    for (int rr = 0; rr < 8; rr++) {
        int r = wid * 8 + rr;
        float ss = 0.f;
        #pragma unroll
        for (int t = 0; t < 4; t++) {
            int c = lane + 32 * t;
            float4 v = t4[(size_t)(row0 + r) * 128 + c];
            ss += v.x * v.x + v.y * v.y + v.z * v.z + v.w * v.w;
            __nv_bfloat162* dst = (__nv_bfloat162*)(A + r * 552 + c * 4);
            dst[0] = __floats2bfloat162_rn(v.x, v.y);
            dst[1] = __floats2bfloat162_rn(v.z, v.w);
        }
        ss = wredsum(ss);
        if (lane == 0) rowss[r] = ss;
    }
    for (int id = tid; id < 128 * 40; id += 512) {
        int r = id / 40, c = 512 + id % 40;
        A[r * 552 + c] = __float2bfloat16(0.f);
    }
    for (int id = tid; id < 512 * 4; id += 512) {
        int k = id >> 2, g = id & 3;
        ((float4*)(Ct + k * 40))[g] = ((const float4*)g_cacheT)[k * 4 + g];
    }
    __syncthreads();

    // stage 2: score MMA  S[128x32] = A(text) @ cacheT — 16 warps, split-k (2 halves of 256)
    {
        int sr = (wid & 7) * 16;          // row tile
        int kh = wid >> 3;                // k half
        wmma::fragment<wmma::accumulator, 16, 16, 16, float> sacc[2];
        wmma::fill_fragment(sacc[0], 0.f);
        wmma::fill_fragment(sacc[1], 0.f);
        for (int k0 = kh * 256; k0 < kh * 256 + 256; k0 += 16) {
            wmma::fragment<wmma::matrix_a, 16, 16, 16, __nv_bfloat16, wmma::row_major> af;
            wmma::load_matrix_sync(af, A + sr * 552 + k0, 552);
            #pragma unroll
            for (int j = 0; j < 2; j++) {
                wmma::fragment<wmma::matrix_b, 16, 16, 16, __nv_bfloat16, wmma::row_major> bf;
                wmma::load_matrix_sync(bf, Ct + k0 * 40 + j * 16, 40);
                wmma::mma_sync(sacc[j], af, bf, sacc[j]);
            }
        }
        float* dstS = (kh == 0) ? Ssm : Ssm2;
        wmma::store_matrix_sync(dstS + sr * 36, sacc[0], 36, wmma::mem_row_major);
        wmma::store_matrix_sync(dstS + sr * 36 + 16, sacc[1], 36, wmma::mem_row_major);
    }
    __syncthreads();

    // stage 3: softmax (sum the two k-halves) -> p into A cols 512..536 (warps 0-7)
    if (wid < 8) {
        for (int rr = 0; rr < 16; rr++) {
            int r = wid * 16 + rr;
            float rinv = 1.f / fmaxf(sqrtf(rowss[r]), 1e-12f);
            float s = (lane < MEM) ? (Ssm[r * 36 + lane] + Ssm2[r * 36 + lane]) * rinv : -1e30f;
            float mx = wredmax(s);
            float e = (lane < MEM) ? expf(s - mx) : 0.f;
            float sum = wredsum(e);
            if (lane < MEM) A[r * 552 + 512 + lane] = __float2bfloat16(e / sum);
        }
    }
    __syncthreads();

    // stage 4: out = ([text|p] @ Bbig) + text
    // 128-col chunks, 2 k-passes of 272; 16 warps as 4x4 grid of 32x32 tiles (2 B/elem)
    int wr = wid & 3, wc = wid >> 2;
    for (int cb = 0; cb < 4; cb++) {
        int col0 = cb * 128;
        wmma::fragment<wmma::accumulator, 16, 16, 16, float> acc[2][2];
        #pragma unroll
        for (int i = 0; i < 2; i++)
            #pragma unroll
            for (int j = 0; j < 2; j++) wmma::fill_fragment(acc[i][j], 0.f);

        #pragma unroll
        for (int kp = 0; kp < 2; kp++) {
            // load Bs = Bbig[kp*272 .. +272)[col0 .. +128)
            for (int id = tid; id < 272 * 16; id += 512) {
                int r = id >> 4, g = id & 15;
                ((float4*)(Bs + r * 136))[g] =
                    ((const float4*)g_Bbig)[(size_t)(kp * 272 + r) * 64 + (col0 >> 3) + g];
            }
            __syncthreads();
            for (int k0 = 0; k0 < 272; k0 += 16) {
                wmma::fragment<wmma::matrix_a, 16, 16, 16, __nv_bfloat16, wmma::row_major> af[2];
                wmma::fragment<wmma::matrix_b, 16, 16, 16, __nv_bfloat16, wmma::row_major> bf[2];
                #pragma unroll
                for (int i = 0; i < 2; i++)
                    wmma::load_matrix_sync(af[i], A + (wr * 32 + i * 16) * 552 + kp * 272 + k0, 552);
                #pragma unroll
                for (int j = 0; j < 2; j++)
                    wmma::load_matrix_sync(bf[j], Bs + k0 * 136 + wc * 32 + j * 16, 136);
                #pragma unroll
                for (int i = 0; i < 2; i++)
                    #pragma unroll
                    for (int j = 0; j < 2; j++)
                        wmma::mma_sync(acc[i][j], af[i], bf[j], acc[i][j]);
            }
            __syncthreads();   // Bs reads done before next kp overwrite / Cs aliasing
        }

        // Cs store + fused residual epilogue
        #pragma unroll
        for (int i = 0; i < 2; i++)
            #pragma unroll
            for (int j = 0; j < 2; j++)
                wmma::store_matrix_sync(Cs + (wr * 32 + i * 16) * 132 + wc * 32 + j * 16,
                                        acc[i][j], 132, wmma::mem_row_major);
        __syncthreads();
        for (int it = 0; it < 8; it++) {
            int id = it * 512 + tid;
            int r = id >> 5, q = id & 31;
            float4 v = *((float4*)&Cs[r * 132 + q * 4]);
            float4 t = t4[(size_t)(row0 + r) * 128 + (col0 >> 2) + q];
            v.x += t.x; v.y += t.y; v.z += t.z; v.w += t.w;
            ((float4*)out)[(size_t)(row0 + r) * 128 + (col0 >> 2) + q] = v;
        }
        __syncthreads();
    }

    // stage 5: loss partial (warp owns 8 rows; out tile is L2-hot)
    {
        const float4* o4 = (const float4*)out;
        float accum = 0.f;
        #pragma unroll
        for (int rr = 0; rr < 8; rr++) {
            int i = row0 + wid * 8 + rr;
            float4 tf[4]; float ss = 0.f;
            #pragma unroll
            for (int t = 0; t < 4; t++) {
                tf[t] = o4[(size_t)i * 128 + lane + 32 * t];
                ss += tf[t].x * tf[t].x + tf[t].y * tf[t].y + tf[t].z * tf[t].z + tf[t].w * tf[t].w;
            }
            ss = wredsum(ss);
            float inv = 1.f / fmaxf(sqrtf(ss), 1e-12f);
            float sa = 0.f;
            #pragma unroll
            for (int t = 0; t < 4; t++) {
                float4 x = t4[(size_t)i * 128 + lane + 32 * t];
                sa += fabsf(tf[t].x * inv - x.x) + fabsf(tf[t].y * inv - x.y) +
                      fabsf(tf[t].z * inv - x.z) + fabsf(tf[t].w * inv - x.w);
            }
            accum += wredsum(sa);
        }
        __shared__ float ws[16];
        if (lane == 0) ws[wid] = accum;
        __syncthreads();
        if (tid == 0) {
            float s = 0.f;
            #pragma unroll
            for (int w = 0; w < 16; w++) s += ws[w];
            g_losspart[blockIdx.x] = s;
        }
    }
}

__global__ void k_loss2(float* __restrict__ out) {
    __shared__ float sh[256];
    int tid = threadIdx.x;
    float s = 0.f;
    for (int id = tid; id < 1024; id += 256) s += g_losspart[id];
    sh[tid] = s;
    __syncthreads();
    for (int off = 128; off > 0; off >>= 1) {
        if (tid < off) sh[tid] += sh[tid + off];
        __syncthreads();
    }
    if (tid == 0) out[(size_t)N_TOK * DIM] = sh[0] * (1.0f / 67108864.0f);
}

// ---------------- fused write (512 threads): img attention + one-hot scatter MMA ----------------
// smem: Bimg f32[64][524] 134144 | CtF f32[512][36] 73728 | Aw f32[32][76] 9728 | Ssm f32[64][36] 9216
__global__ void __launch_bounds__(512) k_write(const float* __restrict__ img) {
    extern __shared__ unsigned char sraw[];
    float* Bimg = (float*)sraw;                             // [64][524]
    float* CtF  = (float*)(sraw + 134144);                  // [512][36]
    float* Aw   = (float*)(sraw + 134144 + 73728);          // [32][76]
    float* Ssm  = (float*)(sraw + 134144 + 73728 + 9728);   // [64][36]
    __shared__ float cnts[32];
    __shared__ float rinv_s[64];
    __shared__ unsigned cm_u[MEM];

    int tid = threadIdx.x, lane = tid & 31, wid = tid >> 5;   // 16 warps
    if (tid < 32) cnts[tid] = 0.f;
    if (tid < MEM) cm_u[tid] = 0u;

    for (int id = tid; id < 512 * 8; id += 512) {
        int k = id >> 3, g = id & 7;
        ((float4*)(CtF + k * 36))[g] = ((const float4*)g_cacheTf)[k * 8 + g];
    }

    float cmreg[MEM];
    #pragma unroll
    for (int m = 0; m < MEM; m++) cmreg[m] = -1e30f;

    wmma::fragment<wmma::accumulator, 16, 16, 8, float> acc[2][2];
    #pragma unroll
    for (int i = 0; i < 2; i++)
        #pragma unroll
        for (int j = 0; j < 2; j++) wmma::fill_fragment(acc[i][j], 0.f);

    const float4* i4 = (const float4*)img;
    for (int tile = blockIdx.x; tile < 2048; tile += gridDim.x) {
        int base = tile * 64;
        #pragma unroll
        for (int rr = 0; rr < 4; rr++) {
            int r = wid * 4 + rr;
            float ss = 0.f;
            #pragma unroll
            for (int t = 0; t < 4; t++) {
                int c = lane + 32 * t;
                float4 v = i4[(size_t)(base + r) * 128 + c];
                *((float4*)&Bimg[r * 524 + c * 4]) = v;
                ss += v.x * v.x + v.y * v.y + v.z * v.z + v.w * v.w;
            }
            ss = wredsum(ss);
            if (lane == 0) rinv_s[r] = rsqrtf(ss);
        }
        for (int id = tid; id < 32 * 76; id += 512) Aw[id] = 0.f;
        __syncthreads();

        // score MMA (tf32 big+small, near-fp32): S[64x32] = Bimg @ CtF (warps 0-7)
        if (wid < 8) {
            int rowt = wid >> 1, colt = wid & 1;
            wmma::fragment<wmma::accumulator, 16, 16, 8, float> sacc;
            wmma::fill_fragment(sacc, 0.f);
            for (int k0 = 0; k0 < 512; k0 += 8) {
                wmma::fragment<wmma::matrix_a, 16, 16, 8, wmma::precision::tf32, wmma::row_major> ab, as;
                wmma::fragment<wmma::matrix_b, 16, 16, 8, wmma::precision::tf32, wmma::row_major> bb, bs;
                wmma::load_matrix_sync(ab, Bimg + (rowt * 16) * 524 + k0, 524);
                wmma::load_matrix_sync(bb, CtF + k0 * 36 + colt * 16, 36);
                #pragma unroll
                for (int t = 0; t < ab.num_elements; t++) {
                    float x = ab.x[t];
                    float big = wmma::__float_to_tf32(x);
                    ab.x[t] = big;
                    as.x[t] = wmma::__float_to_tf32(x - big);
                }
                #pragma unroll
                for (int t = 0; t < bb.num_elements; t++) {
                    float x = bb.x[t];
                    float big = wmma::__float_to_tf32(x);
                    bb.x[t] = big;
                    bs.x[t] = wmma::__float_to_tf32(x - big);
                }
                wmma::mma_sync(sacc, ab, bs, sacc);
                wmma::mma_sync(sacc, as, bb, sacc);
                wmma::mma_sync(sacc, ab, bb, sacc);
            }
            wmma::store_matrix_sync(Ssm + (rowt * 16) * 36 + colt * 16, sacc, 36,
                                    wmma::mem_row_major);
        }
        __syncthreads();

        if (tid < 64) {
            float rv = rinv_s[tid];
            float best = -1e30f; int bi = 0;
            #pragma unroll
            for (int m = 0; m < MEM; m++) {
                float v = Ssm[tid * 36 + m] * rv;
                cmreg[m] = fmaxf(cmreg[m], v);
                if (v > best) { best = v; bi = m; }
            }
            Aw[bi * 76 + tid] = __expf(best) * rv;
            atomicAdd(&cnts[bi], 1.f);
        }
        __syncthreads();

        for (int ks = 0; ks < 8; ks++) {
            int k0 = ks * 8;
            wmma::fragment<wmma::matrix_a, 16, 16, 8, wmma::precision::tf32, wmma::row_major> af[2];
            wmma::fragment<wmma::matrix_b, 16, 16, 8, wmma::precision::tf32, wmma::row_major> bf[2];
            #pragma unroll
            for (int i = 0; i < 2; i++) {
                wmma::load_matrix_sync(af[i], Aw + (i * 16) * 76 + k0, 76);
                #pragma unroll
                for (int t = 0; t < af[i].num_elements; t++)
                    af[i].x[t] = wmma::__float_to_tf32(af[i].x[t]);
            }
            #pragma unroll
            for (int j = 0; j < 2; j++) {
                wmma::load_matrix_sync(bf[j], Bimg + k0 * 524 + wid * 32 + j * 16, 524);
                #pragma unroll
                for (int t = 0; t < bf[j].num_elements; t++)
                    bf[j].x[t] = wmma::__float_to_tf32(bf[j].x[t]);
            }
            #pragma unroll
            for (int i = 0; i < 2; i++)
                #pragma unroll
                for (int j = 0; j < 2; j++)
                    wmma::mma_sync(acc[i][j], af[i], bf[j], acc[i][j]);
        }
        __syncthreads();
    }

    #pragma unroll
    for (int i = 0; i < 2; i++)
        #pragma unroll
        for (int j = 0; j < 2; j++)
            wmma::store_matrix_sync(g_segp + (size_t)blockIdx.x * 16384 + (i * 16) * 512 +
                                    wid * 32 + j * 16, acc[i][j], 512, wmma::mem_row_major);
    if (tid < 32) g_cntp[blockIdx.x * 32 + tid] = cnts[tid];

    if (tid < 64) {
        #pragma unroll
        for (int m = 0; m < MEM; m++) atomicMax(&cm_u[m], f2o(cmreg[m]));
    }
    __syncthreads();
    if (tid < MEM) atomicMax(&g_colmax[tid], cm_u[tid]);
}

// ---------------- cache EMA update + normalize ----------------
__global__ void k_update(const float* __restrict__ cache, float* __restrict__ out) {
    int m = blockIdx.x, d = threadIdx.x;
    float cnt = 0.f;
    for (int b = 0; b < WBLK; b++) cnt += g_cntp[b * 32 + m];
    float s = 0.f;
    for (int b = 0; b < WBLK; b++) s += g_segp[(size_t)b * 16384 + m * 512 + d];
    float cm = o2f(g_colmax[m]);
    s *= __expf(-cm);
    float cv = cache[m * DIM + d];
    float u = (cnt > 0.f) ? (MOM * cv + (1.f - MOM) * s) : cv;
    float v = u * u;
    v = wredsum(v);
    __shared__ float red[16];
    __shared__ float tot;
    if ((threadIdx.x & 31) == 0) red[threadIdx.x >> 5] = v;
    __syncthreads();
    if (threadIdx.x < 32) {
        float t = (threadIdx.x < 16) ? red[threadIdx.x] : 0.f;
        t = wredsum(t);
        if (threadIdx.x == 0) tot = t;
    }
    __syncthreads();
    float inv = 1.f / fmaxf(sqrtf(tot), 1e-12f);
    out[(size_t)N_TOK * DIM + 1 + m * DIM + d] = u * inv;
}

// ---------------- launch ----------------
extern "C" void kernel_launch(void* const* d_in, const int* in_sizes, int n_in,
                              void* d_out, int out_size) {
    const float* text  = (const float*)d_in[0];
    const float* img   = (const float*)d_in[1];
    const float* W     = (const float*)d_in[2];
    const float* cache = (const float*)d_in[3];
    float* out = (float*)d_out;

    const int FUSED_SMEM = 141312 + 78336 + 512;                 // 220160
    const int WRITE_SMEM = 134144 + 73728 + 9728 + 9216;         // 226816

    cudaFuncSetAttribute(k_fused, cudaFuncAttributeMaxDynamicSharedMemorySize, FUSED_SMEM);
    cudaFuncSetAttribute(k_write, cudaFuncAttributeMaxDynamicSharedMemorySize, WRITE_SMEM);

    k_acw2<<<MEM, 256>>>(W, cache);                     // launch 1
    k_prepB<<<(544 * 512 + 255) / 256, 256>>>(W);       // launch 2
    k_prepC<<<(512 * 32 + 255) / 256, 256>>>(cache);    // launch 3
    k_fused<<<1024, 512, FUSED_SMEM>>>(text, out);      // launch 4  <- ncu samples this
    k_write<<<WBLK, 512, WRITE_SMEM>>>(img);            // launch 5
    k_loss2<<<1, 256>>>(out);                           // launch 6
    k_update<<<MEM, 512>>>(cache, out);                 // launch 7
}

// round 17
// speedup vs baseline: 1.6996x; 1.0228x over previous
#include <cuda_runtime.h>
#include <cuda_bf16.h>
#include <mma.h>

#define N_TOK 131072
#define DIM   512
#define MEM   25
#define ALPHA 0.2f
#define MOM   0.8f
#define WBLK  148

using namespace nvcuda;

// ---------------- scratch (device globals; no allocation) ----------------
__device__ __nv_bfloat16 g_Bbig[544 * 512];
__device__ __nv_bfloat16 g_cacheT[512 * 32];
__device__ float    g_cacheTf[512 * 32];
__device__ float    g_ACW2[MEM * DIM];
__device__ unsigned g_colmax[MEM];
__device__ float    g_segp[WBLK * 32 * 512];
__device__ float    g_cntp[WBLK * 32];
__device__ float    g_losspart[1024];

__device__ __forceinline__ unsigned f2o(float f) {
    unsigned u = __float_as_uint(f);
    return (u & 0x80000000u) ? ~u : (u | 0x80000000u);
}
__device__ __forceinline__ float o2f(unsigned u) {
    return __uint_as_float((u & 0x80000000u) ? (u & 0x7FFFFFFFu) : ~u);
}
__device__ __forceinline__ float wredsum(float v) {
    v += __shfl_xor_sync(0xffffffffu, v, 16);
    v += __shfl_xor_sync(0xffffffffu, v, 8);
    v += __shfl_xor_sync(0xffffffffu, v, 4);
    v += __shfl_xor_sync(0xffffffffu, v, 2);
    v += __shfl_xor_sync(0xffffffffu, v, 1);
    return v;
}
__device__ __forceinline__ float wredmax(float v) {
    v = fmaxf(v, __shfl_xor_sync(0xffffffffu, v, 16));
    v = fmaxf(v, __shfl_xor_sync(0xffffffffu, v, 8));
    v = fmaxf(v, __shfl_xor_sync(0xffffffffu, v, 4));
    v = fmaxf(v, __shfl_xor_sync(0xffffffffu, v, 2));
    v = fmaxf(v, __shfl_xor_sync(0xffffffffu, v, 1));
    return v;
}

// ---------------- launch 1: ACW2 + colmax init ----------------
__global__ void k_acw2(const float* __restrict__ W, const float* __restrict__ cache) {
    __shared__ float cs[DIM];
    int m = blockIdx.x;
    if (blockIdx.x == 0 && threadIdx.x < MEM) g_colmax[threadIdx.x] = 0u;
    for (int id = threadIdx.x; id < DIM; id += blockDim.x) cs[id] = cache[m * DIM + id];
    __syncthreads();
    int lane = threadIdx.x & 31, wid = threadIdx.x >> 5;
    for (int j = wid * 64; j < wid * 64 + 64; j++) {
        float d = 0.f;
        #pragma unroll
        for (int t = 0; t < 16; t++) {
            int k = lane + 32 * t;
            d += cs[k] * W[(size_t)j * 1024 + 512 + k];
        }
        d = wredsum(d);
        if (lane == 0) g_ACW2[m * DIM + j] = ALPHA * d;
    }
}

// ---------------- launch 2: Bbig ----------------
__global__ void k_prepB(const float* __restrict__ W) {
    int id = blockIdx.x * 256 + threadIdx.x;
    if (id >= 544 * 512) return;
    int r = id >> 9, o = id & 511;
    float v;
    if (r < 512)            v = ALPHA * W[(size_t)o * 1024 + r];
    else if (r < 512 + MEM) v = g_ACW2[(r - 512) * 512 + o];
    else                    v = 0.f;
    g_Bbig[id] = __float2bfloat16(v);
}

// ---------------- launch 3: cache^T ----------------
__global__ void k_prepC(const float* __restrict__ cache) {
    int id = blockIdx.x * 256 + threadIdx.x;
    if (id >= 512 * 32) return;
    int k = id >> 5, m = id & 31;
    float v = (m < MEM) ? cache[m * DIM + k] : 0.f;
    g_cacheT[id] = __float2bfloat16(v);
    g_cacheTf[id] = v;
}

// ---------------- launch 4 (profiled): 512-thread fused kernel (unchanged from R16) ----------------
// smem: A bf16 [128][552] 141312 | B region 78336:
//   stage4: Bs bf16 [272][136] (73984) then Cs f32 [128][132] (67584)
//   stage2: Ct bf16[512][40] | Ssm f32[128][36] | Ssm2 f32[128][36]
// | rowss f32[128]
__global__ void __launch_bounds__(512) k_fused(const float* __restrict__ text,
                                               float* __restrict__ out) {
    extern __shared__ unsigned char smem_raw[];
    __nv_bfloat16* A  = (__nv_bfloat16*)smem_raw;
    unsigned char* Br = smem_raw + 141312;
    __nv_bfloat16* Bs = (__nv_bfloat16*)Br;                 // [272][136]
    __nv_bfloat16* Ct = (__nv_bfloat16*)Br;                 // [512][40]
    float* Ssm   = (float*)(Br + 40960);                    // [128][36]
    float* Ssm2  = (float*)(Br + 59392);                    // [128][36]
    float* Cs    = (float*)Br;                              // [128][132]
    float* rowss = (float*)(smem_raw + 141312 + 78336);

    int tid = threadIdx.x, lane = tid & 31, wid = tid >> 5;   // 16 warps
    int row0 = blockIdx.x * 128;
    const float4* t4 = (const float4*)text;

    // stage 1: text -> bf16 tile + row sumsq (warp owns 8 rows)
    #pragma unroll 4
    for (int rr = 0; rr < 8; rr++) {
        int r = wid * 8 + rr;
        float ss = 0.f;
        #pragma unroll
        for (int t = 0; t < 4; t++) {
            int c = lane + 32 * t;
            float4 v = t4[(size_t)(row0 + r) * 128 + c];
            ss += v.x * v.x + v.y * v.y + v.z * v.z + v.w * v.w;
            __nv_bfloat162* dst = (__nv_bfloat162*)(A + r * 552 + c * 4);
            dst[0] = __floats2bfloat162_rn(v.x, v.y);
            dst[1] = __floats2bfloat162_rn(v.z, v.w);
        }
        ss = wredsum(ss);
        if (lane == 0) rowss[r] = ss;
    }
    for (int id = tid; id < 128 * 40; id += 512) {
        int r = id / 40, c = 512 + id % 40;
        A[r * 552 + c] = __float2bfloat16(0.f);
    }
    for (int id = tid; id < 512 * 4; id += 512) {
        int k = id >> 2, g = id & 3;
        ((float4*)(Ct + k * 40))[g] = ((const float4*)g_cacheT)[k * 4 + g];
    }
    __syncthreads();

    // stage 2: score MMA — 16 warps, split-k (2 halves of 256)
    {
        int sr = (wid & 7) * 16;
        int kh = wid >> 3;
        wmma::fragment<wmma::accumulator, 16, 16, 16, float> sacc[2];
        wmma::fill_fragment(sacc[0], 0.f);
        wmma::fill_fragment(sacc[1], 0.f);
        for (int k0 = kh * 256; k0 < kh * 256 + 256; k0 += 16) {
            wmma::fragment<wmma::matrix_a, 16, 16, 16, __nv_bfloat16, wmma::row_major> af;
            wmma::load_matrix_sync(af, A + sr * 552 + k0, 552);
            #pragma unroll
            for (int j = 0; j < 2; j++) {
                wmma::fragment<wmma::matrix_b, 16, 16, 16, __nv_bfloat16, wmma::row_major> bf;
                wmma::load_matrix_sync(bf, Ct + k0 * 40 + j * 16, 40);
                wmma::mma_sync(sacc[j], af, bf, sacc[j]);
            }
        }
        float* dstS = (kh == 0) ? Ssm : Ssm2;
        wmma::store_matrix_sync(dstS + sr * 36, sacc[0], 36, wmma::mem_row_major);
        wmma::store_matrix_sync(dstS + sr * 36 + 16, sacc[1], 36, wmma::mem_row_major);
    }
    __syncthreads();

    // stage 3: softmax (sum halves) -> p into A cols 512..536 (warps 0-7)
    if (wid < 8) {
        for (int rr = 0; rr < 16; rr++) {
            int r = wid * 16 + rr;
            float rinv = 1.f / fmaxf(sqrtf(rowss[r]), 1e-12f);
            float s = (lane < MEM) ? (Ssm[r * 36 + lane] + Ssm2[r * 36 + lane]) * rinv : -1e30f;
            float mx = wredmax(s);
            float e = (lane < MEM) ? expf(s - mx) : 0.f;
            float sum = wredsum(e);
            if (lane < MEM) A[r * 552 + 512 + lane] = __float2bfloat16(e / sum);
        }
    }
    __syncthreads();

    // stage 4: out = ([text|p] @ Bbig) + text; 128-col chunks, 2 k-passes, 4x4 grid of 32x32 tiles
    int wr = wid & 3, wc = wid >> 2;
    for (int cb = 0; cb < 4; cb++) {
        int col0 = cb * 128;
        wmma::fragment<wmma::accumulator, 16, 16, 16, float> acc[2][2];
        #pragma unroll
        for (int i = 0; i < 2; i++)
            #pragma unroll
            for (int j = 0; j < 2; j++) wmma::fill_fragment(acc[i][j], 0.f);

        #pragma unroll
        for (int kp = 0; kp < 2; kp++) {
            for (int id = tid; id < 272 * 16; id += 512) {
                int r = id >> 4, g = id & 15;
                ((float4*)(Bs + r * 136))[g] =
                    ((const float4*)g_Bbig)[(size_t)(kp * 272 + r) * 64 + (col0 >> 3) + g];
            }
            __syncthreads();
            for (int k0 = 0; k0 < 272; k0 += 16) {
                wmma::fragment<wmma::matrix_a, 16, 16, 16, __nv_bfloat16, wmma::row_major> af[2];
                wmma::fragment<wmma::matrix_b, 16, 16, 16, __nv_bfloat16, wmma::row_major> bf[2];
                #pragma unroll
                for (int i = 0; i < 2; i++)
                    wmma::load_matrix_sync(af[i], A + (wr * 32 + i * 16) * 552 + kp * 272 + k0, 552);
                #pragma unroll
                for (int j = 0; j < 2; j++)
                    wmma::load_matrix_sync(bf[j], Bs + k0 * 136 + wc * 32 + j * 16, 136);
                #pragma unroll
                for (int i = 0; i < 2; i++)
                    #pragma unroll
                    for (int j = 0; j < 2; j++)
                        wmma::mma_sync(acc[i][j], af[i], bf[j], acc[i][j]);
            }
            __syncthreads();
        }

        #pragma unroll
        for (int i = 0; i < 2; i++)
            #pragma unroll
            for (int j = 0; j < 2; j++)
                wmma::store_matrix_sync(Cs + (wr * 32 + i * 16) * 132 + wc * 32 + j * 16,
                                        acc[i][j], 132, wmma::mem_row_major);
        __syncthreads();
        for (int it = 0; it < 8; it++) {
            int id = it * 512 + tid;
            int r = id >> 5, q = id & 31;
            float4 v = *((float4*)&Cs[r * 132 + q * 4]);
            float4 t = t4[(size_t)(row0 + r) * 128 + (col0 >> 2) + q];
            v.x += t.x; v.y += t.y; v.z += t.z; v.w += t.w;
            ((float4*)out)[(size_t)(row0 + r) * 128 + (col0 >> 2) + q] = v;
        }
        __syncthreads();
    }

    // stage 5: loss partial (warp owns 8 rows; out tile is L2-hot)
    {
        const float4* o4 = (const float4*)out;
        float accum = 0.f;
        #pragma unroll
        for (int rr = 0; rr < 8; rr++) {
            int i = row0 + wid * 8 + rr;
            float4 tf[4]; float ss = 0.f;
            #pragma unroll
            for (int t = 0; t < 4; t++) {
                tf[t] = o4[(size_t)i * 128 + lane + 32 * t];
                ss += tf[t].x * tf[t].x + tf[t].y * tf[t].y + tf[t].z * tf[t].z + tf[t].w * tf[t].w;
            }
            ss = wredsum(ss);
            float inv = 1.f / fmaxf(sqrtf(ss), 1e-12f);
            float sa = 0.f;
            #pragma unroll
            for (int t = 0; t < 4; t++) {
                float4 x = t4[(size_t)i * 128 + lane + 32 * t];
                sa += fabsf(tf[t].x * inv - x.x) + fabsf(tf[t].y * inv - x.y) +
                      fabsf(tf[t].z * inv - x.z) + fabsf(tf[t].w * inv - x.w);
            }
            accum += wredsum(sa);
        }
        __shared__ float ws[16];
        if (lane == 0) ws[wid] = accum;
        __syncthreads();
        if (tid == 0) {
            float s = 0.f;
            #pragma unroll
            for (int w = 0; w < 16; w++) s += ws[w];
            g_losspart[blockIdx.x] = s;
        }
    }
}

__global__ void k_loss2(float* __restrict__ out) {
    __shared__ float sh[256];
    int tid = threadIdx.x;
    float s = 0.f;
    for (int id = tid; id < 1024; id += 256) s += g_losspart[id];
    sh[tid] = s;
    __syncthreads();
    for (int off = 128; off > 0; off >>= 1) {
        if (tid < off) sh[tid] += sh[tid + off];
        __syncthreads();
    }
    if (tid == 0) out[(size_t)N_TOK * DIM] = sh[0] * (1.0f / 67108864.0f);
}

// ---------------- fused write (512 threads): split-k score across 16 warps ----------------
// smem: Bimg f32[64][524] 134144 | CtF f32[512][36] 73728
//   | UNION 9216 { Ssm2 f32[64][36] (score->argmax-read) / Aw f32[32][68] (argmax-write->scatter) }
//   | Ssm f32[64][36] 9216      total 226304
__global__ void __launch_bounds__(512) k_write(const float* __restrict__ img) {
    extern __shared__ unsigned char sraw[];
    float* Bimg = (float*)sraw;                             // [64][524]
    float* CtF  = (float*)(sraw + 134144);                  // [512][36]
    float* Ssm2 = (float*)(sraw + 134144 + 73728);          // [64][36]  (aliases Aw)
    float* Aw   = (float*)(sraw + 134144 + 73728);          // [32][68]  (aliases Ssm2)
    float* Ssm  = (float*)(sraw + 134144 + 73728 + 9216);   // [64][36]
    __shared__ float cnts[32];
    __shared__ float rinv_s[64];
    __shared__ unsigned cm_u[MEM];

    int tid = threadIdx.x, lane = tid & 31, wid = tid >> 5;   // 16 warps
    if (tid < 32) cnts[tid] = 0.f;
    if (tid < MEM) cm_u[tid] = 0u;

    for (int id = tid; id < 512 * 8; id += 512) {
        int k = id >> 3, g = id & 7;
        ((float4*)(CtF + k * 36))[g] = ((const float4*)g_cacheTf)[k * 8 + g];
    }

    float cmreg[MEM];
    #pragma unroll
    for (int m = 0; m < MEM; m++) cmreg[m] = -1e30f;

    wmma::fragment<wmma::accumulator, 16, 16, 8, float> acc[2][2];
    #pragma unroll
    for (int i = 0; i < 2; i++)
        #pragma unroll
        for (int j = 0; j < 2; j++) wmma::fill_fragment(acc[i][j], 0.f);

    const float4* i4 = (const float4*)img;
    for (int tile = blockIdx.x; tile < 2048; tile += gridDim.x) {
        int base = tile * 64;
        // load tile + fused row sumsq (warp owns 4 rows)
        #pragma unroll
        for (int rr = 0; rr < 4; rr++) {
            int r = wid * 4 + rr;
            float ss = 0.f;
            #pragma unroll
            for (int t = 0; t < 4; t++) {
                int c = lane + 32 * t;
                float4 v = i4[(size_t)(base + r) * 128 + c];
                *((float4*)&Bimg[r * 524 + c * 4]) = v;
                ss += v.x * v.x + v.y * v.y + v.z * v.z + v.w * v.w;
            }
            ss = wredsum(ss);
            if (lane == 0) rinv_s[r] = rsqrtf(ss);
        }
        __syncthreads();

        // score MMA (tf32 big+small) — 16 warps: 8 S-tiles x 2 k-halves of 256
        {
            int st = wid & 7;
            int rowt = st >> 1, colt = st & 1;
            int kh = wid >> 3;
            wmma::fragment<wmma::accumulator, 16, 16, 8, float> sacc;
            wmma::fill_fragment(sacc, 0.f);
            for (int k0 = kh * 256; k0 < kh * 256 + 256; k0 += 8) {
                wmma::fragment<wmma::matrix_a, 16, 16, 8, wmma::precision::tf32, wmma::row_major> ab, as;
                wmma::fragment<wmma::matrix_b, 16, 16, 8, wmma::precision::tf32, wmma::row_major> bb, bs;
                wmma::load_matrix_sync(ab, Bimg + (rowt * 16) * 524 + k0, 524);
                wmma::load_matrix_sync(bb, CtF + k0 * 36 + colt * 16, 36);
                #pragma unroll
                for (int t = 0; t < ab.num_elements; t++) {
                    float x = ab.x[t];
                    float big = wmma::__float_to_tf32(x);
                    ab.x[t] = big;
                    as.x[t] = wmma::__float_to_tf32(x - big);
                }
                #pragma unroll
                for (int t = 0; t < bb.num_elements; t++) {
                    float x = bb.x[t];
                    float big = wmma::__float_to_tf32(x);
                    bb.x[t] = big;
                    bs.x[t] = wmma::__float_to_tf32(x - big);
                }
                wmma::mma_sync(sacc, ab, bs, sacc);
                wmma::mma_sync(sacc, as, bb, sacc);
                wmma::mma_sync(sacc, ab, bb, sacc);
            }
            float* dstS = (kh == 0) ? Ssm : Ssm2;
            wmma::store_matrix_sync(dstS + (rowt * 16) * 36 + colt * 16, sacc, 36,
                                    wmma::mem_row_major);
        }
        __syncthreads();

        // argmax phase 1: read scores (Ssm + Ssm2), compute best slot + weight
        float w_val = 0.f; int bi_reg = 0;
        if (tid < 64) {
            float rv = rinv_s[tid];
            float best = -1e30f; int bi = 0;
            #pragma unroll
            for (int m = 0; m < MEM; m++) {
                float v = (Ssm[tid * 36 + m] + Ssm2[tid * 36 + m]) * rv;
                cmreg[m] = fmaxf(cmreg[m], v);
                if (v > best) { best = v; bi = m; }
            }
            w_val = __expf(best) * rv;
            bi_reg = bi;
            atomicAdd(&cnts[bi], 1.f);
        }
        __syncthreads();   // all Ssm2 reads done before Aw writes (aliased region)

        // argmax phase 2: write one-hot weight column (zero-fills Aw)
        if (tid < 64) {
            #pragma unroll
            for (int m = 0; m < 32; m++)
                Aw[m * 68 + tid] = (m == bi_reg) ? w_val : 0.f;
        }
        __syncthreads();

        // scatter MMA: acc += Aw(one-hot) @ Bimg  (warp covers cols wid*32..wid*32+31)
        for (int ks = 0; ks < 8; ks++) {
            int k0 = ks * 8;
            wmma::fragment<wmma::matrix_a, 16, 16, 8, wmma::precision::tf32, wmma::row_major> af[2];
            wmma::fragment<wmma::matrix_b, 16, 16, 8, wmma::precision::tf32, wmma::row_major> bf[2];
            #pragma unroll
            for (int i = 0; i < 2; i++) {
                wmma::load_matrix_sync(af[i], Aw + (i * 16) * 68 + k0, 68);
                #pragma unroll
                for (int t = 0; t < af[i].num_elements; t++)
                    af[i].x[t] = wmma::__float_to_tf32(af[i].x[t]);
            }
            #pragma unroll
            for (int j = 0; j < 2; j++) {
                wmma::load_matrix_sync(bf[j], Bimg + k0 * 524 + wid * 32 + j * 16, 524);
                #pragma unroll
                for (int t = 0; t < bf[j].num_elements; t++)
                    bf[j].x[t] = wmma::__float_to_tf32(bf[j].x[t]);
            }
            #pragma unroll
            for (int i = 0; i < 2; i++)
                #pragma unroll
                for (int j = 0; j < 2; j++)
                    wmma::mma_sync(acc[i][j], af[i], bf[j], acc[i][j]);
        }
        __syncthreads();
    }

    #pragma unroll
    for (int i = 0; i < 2; i++)
        #pragma unroll
        for (int j = 0; j < 2; j++)
            wmma::store_matrix_sync(g_segp + (size_t)blockIdx.x * 16384 + (i * 16) * 512 +
                                    wid * 32 + j * 16, acc[i][j], 512, wmma::mem_row_major);
    if (tid < 32) g_cntp[blockIdx.x * 32 + tid] = cnts[tid];

    if (tid < 64) {
        #pragma unroll
        for (int m = 0; m < MEM; m++) atomicMax(&cm_u[m], f2o(cmreg[m]));
    }
    __syncthreads();
    if (tid < MEM) atomicMax(&g_colmax[tid], cm_u[tid]);
}

// ---------------- cache EMA update + normalize ----------------
__global__ void k_update(const float* __restrict__ cache, float* __restrict__ out) {
    int m = blockIdx.x, d = threadIdx.x;
    float cnt = 0.f;
    for (int b = 0; b < WBLK; b++) cnt += g_cntp[b * 32 + m];
    float s = 0.f;
    for (int b = 0; b < WBLK; b++) s += g_segp[(size_t)b * 16384 + m * 512 + d];
    float cm = o2f(g_colmax[m]);
    s *= __expf(-cm);
    float cv = cache[m * DIM + d];
    float u = (cnt > 0.f) ? (MOM * cv + (1.f - MOM) * s) : cv;
    float v = u * u;
    v = wredsum(v);
    __shared__ float red[16];
    __shared__ float tot;
    if ((threadIdx.x & 31) == 0) red[threadIdx.x >> 5] = v;
    __syncthreads();
    if (threadIdx.x < 32) {
        float t = (threadIdx.x < 16) ? red[threadIdx.x] : 0.f;
        t = wredsum(t);
        if (threadIdx.x == 0) tot = t;
    }
    __syncthreads();
    float inv = 1.f / fmaxf(sqrtf(tot), 1e-12f);
    out[(size_t)N_TOK * DIM + 1 + m * DIM + d] = u * inv;
}

// ---------------- launch ----------------
extern "C" void kernel_launch(void* const* d_in, const int* in_sizes, int n_in,
                              void* d_out, int out_size) {
    const float* text  = (const float*)d_in[0];
    const float* img   = (const float*)d_in[1];
    const float* W     = (const float*)d_in[2];
    const float* cache = (const float*)d_in[3];
    float* out = (float*)d_out;

    const int FUSED_SMEM = 141312 + 78336 + 512;                 // 220160
    const int WRITE_SMEM = 134144 + 73728 + 9216 + 9216;         // 226304

    cudaFuncSetAttribute(k_fused, cudaFuncAttributeMaxDynamicSharedMemorySize, FUSED_SMEM);
    cudaFuncSetAttribute(k_write, cudaFuncAttributeMaxDynamicSharedMemorySize, WRITE_SMEM);

    k_acw2<<<MEM, 256>>>(W, cache);                     // launch 1
    k_prepB<<<(544 * 512 + 255) / 256, 256>>>(W);       // launch 2
    k_prepC<<<(512 * 32 + 255) / 256, 256>>>(cache);    // launch 3
    k_fused<<<1024, 512, FUSED_SMEM>>>(text, out);      // launch 4  <- ncu samples this
    k_write<<<WBLK, 512, WRITE_SMEM>>>(img);            // launch 5
    k_loss2<<<1, 256>>>(out);                           // launch 6
    k_update<<<MEM, 512>>>(cache, out);                 // launch 7
}